// round 1
// baseline (speedup 1.0000x reference)
#include <cuda_runtime.h>

#define BATCH 2
#define SEQ   2048
#define DIM   1024
#define NH    16
#define HD    64
#define MAXD  128

// Scratch (static device allocations are allowed)
__device__ float g_q[BATCH * NH * SEQ * HD];
__device__ float g_k[BATCH * NH * SEQ * HD];
__device__ float g_v[BATCH * NH * SEQ * HD];
__device__ float g_att[BATCH * SEQ * DIM];

// ---------------------------------------------------------------------------
// SGEMM: C = A[M, K] @ W[N, K]^T + bias, M = BATCH*SEQ, N = K = DIM
// 128x128 tile, BK=8, 256 threads, 8x8 microtile.
// SCATTER=1: write C in [B, H, S, Hd] layout (for Q/K/V).
// SCATTER=0: write C row-major [M, N].
// ---------------------------------------------------------------------------
template <int SCATTER>
__global__ __launch_bounds__(256)
void gemm_kernel(const float* __restrict__ A, const float* __restrict__ W,
                 const float* __restrict__ bias, float* __restrict__ C)
{
    __shared__ float As[8][128];
    __shared__ float Bs[8][128];

    const int tid = threadIdx.x;
    const int tx = tid & 15;
    const int ty = tid >> 4;
    const int m0 = blockIdx.y * 128;
    const int n0 = blockIdx.x * 128;

    const int lrow = tid >> 1;          // 0..127
    const int lcg  = (tid & 1) * 4;     // 0 or 4

    const float* Aptr = A + (size_t)(m0 + lrow) * DIM + lcg;
    const float* Wptr = W + (size_t)(n0 + lrow) * DIM + lcg;

    float acc[8][8];
#pragma unroll
    for (int i = 0; i < 8; i++)
#pragma unroll
        for (int j = 0; j < 8; j++) acc[i][j] = 0.0f;

    for (int k0 = 0; k0 < DIM; k0 += 8) {
        float4 av = *(const float4*)(Aptr + k0);
        float4 wv = *(const float4*)(Wptr + k0);
        As[lcg + 0][lrow] = av.x; As[lcg + 1][lrow] = av.y;
        As[lcg + 2][lrow] = av.z; As[lcg + 3][lrow] = av.w;
        Bs[lcg + 0][lrow] = wv.x; Bs[lcg + 1][lrow] = wv.y;
        Bs[lcg + 2][lrow] = wv.z; Bs[lcg + 3][lrow] = wv.w;
        __syncthreads();

#pragma unroll
        for (int kk = 0; kk < 8; kk++) {
            float4 a0 = ((const float4*)As[kk])[ty * 2 + 0];
            float4 a1 = ((const float4*)As[kk])[ty * 2 + 1];
            float4 b0 = ((const float4*)Bs[kk])[tx * 2 + 0];
            float4 b1 = ((const float4*)Bs[kk])[tx * 2 + 1];
            float af[8] = {a0.x, a0.y, a0.z, a0.w, a1.x, a1.y, a1.z, a1.w};
            float bf[8] = {b0.x, b0.y, b0.z, b0.w, b1.x, b1.y, b1.z, b1.w};
#pragma unroll
            for (int i = 0; i < 8; i++)
#pragma unroll
                for (int j = 0; j < 8; j++)
                    acc[i][j] = fmaf(af[i], bf[j], acc[i][j]);
        }
        __syncthreads();
    }

#pragma unroll
    for (int i = 0; i < 8; i++) {
        const int m = m0 + ty * 8 + i;
        const int b = m / SEQ;
        const int s = m - b * SEQ;
#pragma unroll
        for (int jj = 0; jj < 2; jj++) {
            const int n = n0 + tx * 8 + jj * 4;
            float4 v;
            v.x = acc[i][jj * 4 + 0] + bias[n + 0];
            v.y = acc[i][jj * 4 + 1] + bias[n + 1];
            v.z = acc[i][jj * 4 + 2] + bias[n + 2];
            v.w = acc[i][jj * 4 + 3] + bias[n + 3];
            if (SCATTER) {
                const int h = n / HD;
                const int d = n - h * HD;
                *(float4*)&C[(((size_t)b * NH + h) * SEQ + s) * HD + d] = v;
            } else {
                *(float4*)&C[(size_t)m * DIM + n] = v;
            }
        }
    }
}

// ---------------------------------------------------------------------------
// Fused flash-attention with relative position bias.
// One CTA per (q-tile of 64, head, batch). 256 threads, 4x4 microtile.
// ---------------------------------------------------------------------------
__global__ __launch_bounds__(256)
void attn_kernel(const float* __restrict__ rel_emb)
{
    extern __shared__ float sm[];
    float* Qs = sm;                  // [HD][64], transposed: Qs[d*64 + r]
    float* Ks = Qs + 64 * 64;        // [HD][64], transposed: Ks[d*64 + c]
    float* Vs = Ks + 64 * 64;        // [64][HD]
    float* Ss = Vs + 64 * HD;        // [64][65]
    float* rowm = Ss + 64 * 65;      // [64]
    float* rowl = rowm + 64;         // [64]
    float* rowf = rowl + 64;         // [64]

    const int tid = threadIdx.x;
    const int tx = tid & 15;
    const int ty = tid >> 4;
    const int qt = blockIdx.x;
    const int h  = blockIdx.y;
    const int b  = blockIdx.z;

    const float* Qg    = g_q + (((size_t)b * NH + h) * SEQ + qt * 64) * HD;
    const float* Kbase = g_k + ((size_t)b * NH + h) * SEQ * HD;
    const float* Vbase = g_v + ((size_t)b * NH + h) * SEQ * HD;

    // Load Q tile (64x64) transposed into shared
#pragma unroll
    for (int i = 0; i < 4; i++) {
        const int f  = tid + i * 256;       // float4 index 0..1023
        const int r  = f >> 4;              // row 0..63
        const int c4 = (f & 15) * 4;        // col base
        float4 v = ((const float4*)Qg)[f];
        Qs[(c4 + 0) * 64 + r] = v.x;
        Qs[(c4 + 1) * 64 + r] = v.y;
        Qs[(c4 + 2) * 64 + r] = v.z;
        Qs[(c4 + 3) * 64 + r] = v.w;
    }
    if (tid < 64) { rowm[tid] = -1e30f; rowl[tid] = 0.0f; }

    float acc[4][4];
#pragma unroll
    for (int i = 0; i < 4; i++)
#pragma unroll
        for (int j = 0; j < 4; j++) acc[i][j] = 0.0f;

    for (int kt = 0; kt < SEQ / 64; kt++) {
        const float* Kg = Kbase + (size_t)kt * 64 * HD;
        const float* Vg = Vbase + (size_t)kt * 64 * HD;
        __syncthreads();   // previous iter's PV readers done before overwrite
#pragma unroll
        for (int i = 0; i < 4; i++) {
            const int f  = tid + i * 256;
            const int r  = f >> 4;
            const int c4 = (f & 15) * 4;
            float4 v = ((const float4*)Kg)[f];
            Ks[(c4 + 0) * 64 + r] = v.x;
            Ks[(c4 + 1) * 64 + r] = v.y;
            Ks[(c4 + 2) * 64 + r] = v.z;
            Ks[(c4 + 3) * 64 + r] = v.w;
            ((float4*)Vs)[f] = ((const float4*)Vg)[f];
        }
        __syncthreads();

        // Scores: S[r][c] = sum_d Q[r][d] * K[c][d]
        float s[4][4];
#pragma unroll
        for (int i = 0; i < 4; i++)
#pragma unroll
            for (int j = 0; j < 4; j++) s[i][j] = 0.0f;

#pragma unroll 8
        for (int d = 0; d < 64; d++) {
            float4 a  = ((const float4*)(Qs + d * 64))[ty];
            float4 bb = ((const float4*)(Ks + d * 64))[tx];
            float af[4] = {a.x, a.y, a.z, a.w};
            float bf[4] = {bb.x, bb.y, bb.z, bb.w};
#pragma unroll
            for (int i = 0; i < 4; i++)
#pragma unroll
                for (int j = 0; j < 4; j++)
                    s[i][j] = fmaf(af[i], bf[j], s[i][j]);
        }
#pragma unroll
        for (int i = 0; i < 4; i++)
#pragma unroll
            for (int j = 0; j < 4; j++)
                Ss[(ty * 4 + i) * 65 + tx * 4 + j] = s[i][j] * 0.125f;
        __syncthreads();

        // Online softmax, one thread per query row
        if (tid < 64) {
            const int r  = tid;
            const int qi = qt * 64 + r;
            float* row = Ss + r * 65;
            const float mo = rowm[r];
            float mn = mo;
            const int kbase = kt * 64;
#pragma unroll
            for (int k2 = 0; k2 < 64; k2++) {
                int dlt = qi - (kbase + k2);
                dlt = max(-MAXD, min(MAXD, dlt));
                float sv = row[k2] + __ldg(&rel_emb[(dlt + MAXD) * NH + h]);
                row[k2] = sv;
                mn = fmaxf(mn, sv);
            }
            const float fac = __expf(mo - mn);
            float ll = rowl[r] * fac;
#pragma unroll
            for (int k2 = 0; k2 < 64; k2++) {
                float p = __expf(row[k2] - mn);
                row[k2] = p;
                ll += p;
            }
            rowm[r] = mn;
            rowl[r] = ll;
            rowf[r] = fac;
        }
        __syncthreads();

        // Rescale accumulators and accumulate P @ V
#pragma unroll
        for (int i = 0; i < 4; i++) {
            const float fac = rowf[ty * 4 + i];
#pragma unroll
            for (int j = 0; j < 4; j++) acc[i][j] *= fac;
        }
#pragma unroll 8
        for (int k2 = 0; k2 < 64; k2++) {
            float4 v4 = ((const float4*)(Vs + k2 * HD))[tx];
            float vf[4] = {v4.x, v4.y, v4.z, v4.w};
#pragma unroll
            for (int i = 0; i < 4; i++) {
                const float p = Ss[(ty * 4 + i) * 65 + k2];
#pragma unroll
                for (int j = 0; j < 4; j++)
                    acc[i][j] = fmaf(p, vf[j], acc[i][j]);
            }
        }
    }

    // Epilogue: normalize and write in [B, S, H*Hd] layout
#pragma unroll
    for (int i = 0; i < 4; i++) {
        const int r  = ty * 4 + i;
        const int qi = qt * 64 + r;
        const float inv = 1.0f / rowl[r];
        float4 v;
        v.x = acc[i][0] * inv;
        v.y = acc[i][1] * inv;
        v.z = acc[i][2] * inv;
        v.w = acc[i][3] * inv;
        *(float4*)&g_att[(((size_t)b * SEQ + qi) * NH + h) * HD + tx * 4] = v;
    }
}

// ---------------------------------------------------------------------------
extern "C" void kernel_launch(void* const* d_in, const int* in_sizes, int n_in,
                              void* d_out, int out_size)
{
    const float* x   = (const float*)d_in[0];
    const float* Wq  = (const float*)d_in[1];
    const float* bq  = (const float*)d_in[2];
    const float* Wk  = (const float*)d_in[3];
    const float* bk  = (const float*)d_in[4];
    const float* Wv  = (const float*)d_in[5];
    const float* bv  = (const float*)d_in[6];
    const float* Wo  = (const float*)d_in[7];
    const float* bo  = (const float*)d_in[8];
    const float* rel = (const float*)d_in[9];
    float* out = (float*)d_out;

    float *q, *k, *v, *att;
    cudaGetSymbolAddress((void**)&q,   g_q);
    cudaGetSymbolAddress((void**)&k,   g_k);
    cudaGetSymbolAddress((void**)&v,   g_v);
    cudaGetSymbolAddress((void**)&att, g_att);

    dim3 gg(DIM / 128, (BATCH * SEQ) / 128);
    gemm_kernel<1><<<gg, 256>>>(x, Wq, bq, q);
    gemm_kernel<1><<<gg, 256>>>(x, Wk, bk, k);
    gemm_kernel<1><<<gg, 256>>>(x, Wv, bv, v);

    const size_t smem = (size_t)(64 * 64 * 3 + 64 * 65 + 3 * 64) * sizeof(float);
    cudaFuncSetAttribute(attn_kernel, cudaFuncAttributeMaxDynamicSharedMemorySize, (int)smem);
    dim3 ga(SEQ / 64, NH, BATCH);
    attn_kernel<<<ga, 256, smem>>>(rel);

    gemm_kernel<0><<<gg, 256>>>(att, Wo, bo, out);
}

// round 4
// speedup vs baseline: 1.9675x; 1.9675x over previous
#include <cuda_runtime.h>
#include <cuda_bf16.h>
#include <cstdint>

#define BATCH 2
#define SEQ   2048
#define DIM   1024
#define NH    16
#define HD    64
#define MAXD  128
#define MTOT  (BATCH * SEQ)

typedef __nv_bfloat16 bf16;

// Scratch (static device allocations are allowed)
__device__ float g_q[MTOT * DIM];
__device__ float g_k[MTOT * DIM];
__device__ float g_v[MTOT * DIM];
__device__ float g_att[MTOT * DIM];
__device__ bf16  g_xh[MTOT * DIM];
__device__ bf16  g_xl[MTOT * DIM];
__device__ bf16  g_wh[4 * DIM * DIM];
__device__ bf16  g_wl[4 * DIM * DIM];
__device__ bf16  g_ath[MTOT * DIM];
__device__ bf16  g_atl[MTOT * DIM];

// ---------------------------------------------------------------------------
// helpers
// ---------------------------------------------------------------------------
__device__ __forceinline__ uint32_t smem_u32(const void* p) {
    uint32_t a;
    asm("{ .reg .u64 t; cvta.to.shared.u64 t, %1; cvt.u32.u64 %0, t; }" : "=r"(a) : "l"(p));
    return a;
}

__device__ __forceinline__ void ldsm4(uint32_t* r, uint32_t addr) {
    asm volatile("ldmatrix.sync.aligned.m8n8.x4.shared.b16 {%0,%1,%2,%3}, [%4];"
                 : "=r"(r[0]), "=r"(r[1]), "=r"(r[2]), "=r"(r[3]) : "r"(addr));
}

__device__ __forceinline__ void mma_bf(float* d, const uint32_t* a, uint32_t b0, uint32_t b1) {
    asm volatile("mma.sync.aligned.m16n8k16.row.col.f32.bf16.bf16.f32 "
                 "{%0,%1,%2,%3}, {%4,%5,%6,%7}, {%8,%9}, {%0,%1,%2,%3};"
                 : "+f"(d[0]), "+f"(d[1]), "+f"(d[2]), "+f"(d[3])
                 : "r"(a[0]), "r"(a[1]), "r"(a[2]), "r"(a[3]), "r"(b0), "r"(b1));
}

__device__ __forceinline__ uint32_t pack_bf2(bf16 a, bf16 b) {
    __nv_bfloat162 t(a, b);
    return *reinterpret_cast<uint32_t*>(&t);
}

// ---------------------------------------------------------------------------
// split fp32 -> bf16 hi/lo
// ---------------------------------------------------------------------------
__global__ __launch_bounds__(256)
void split_kernel(const float* __restrict__ in, bf16* __restrict__ hi,
                  bf16* __restrict__ lo, int n4)
{
    int i = blockIdx.x * blockDim.x + threadIdx.x;
    if (i >= n4) return;
    float4 v = ((const float4*)in)[i];
    float f[4] = {v.x, v.y, v.z, v.w};
    bf16 h[4], l[4];
#pragma unroll
    for (int j = 0; j < 4; j++) {
        h[j] = __float2bfloat16_rn(f[j]);
        l[j] = __float2bfloat16_rn(f[j] - __bfloat162float(h[j]));
    }
    uint2 hv = make_uint2(pack_bf2(h[0], h[1]), pack_bf2(h[2], h[3]));
    uint2 lv = make_uint2(pack_bf2(l[0], l[1]), pack_bf2(l[2], l[3]));
    ((uint2*)hi)[i] = hv;
    ((uint2*)lo)[i] = lv;
}

// ---------------------------------------------------------------------------
// HMMA split-bf16 GEMM: C = A[M,1024] @ W[N,1024]^T + bias
// 128x128x64 tile, 8 warps (4M x 2N), warp does 32x64 via m16n8k16.
// ---------------------------------------------------------------------------
#define BM 128
#define BN 128
#define BK 64
#define LDT 72   // padded smem row stride (bf16)
#define SMEM_GEMM (4 * BM * LDT * 2)   // 73728 bytes

template <int SCATTER>
__device__ __forceinline__ void gemm_mma_body(
    const bf16* __restrict__ Ah, const bf16* __restrict__ Al,
    const bf16* __restrict__ Wh, const bf16* __restrict__ Wl,
    const float* __restrict__ bias, float* __restrict__ C)
{
    extern __shared__ __align__(16) char smem[];
    bf16* sAh = (bf16*)smem;
    bf16* sAl = sAh + BM * LDT;
    bf16* sWh = sAl + BM * LDT;
    bf16* sWl = sWh + BN * LDT;

    const int tid  = threadIdx.x;
    const int lane = tid & 31;
    const int wid  = tid >> 5;
    const int wm   = wid & 3;     // 0..3 -> m offset 32*wm
    const int wn   = wid >> 2;    // 0..1 -> n offset 64*wn
    const int m0   = blockIdx.y * BM;
    const int n0   = blockIdx.x * BN;

    float d[2][8][4];
#pragma unroll
    for (int i = 0; i < 2; i++)
#pragma unroll
        for (int j = 0; j < 8; j++)
#pragma unroll
            for (int t = 0; t < 4; t++) d[i][j][t] = 0.0f;

    // ldmatrix lane-address components
    const int aRow = wm * 32 + (lane & 15);
    const int aK   = (lane >> 4) * 8;
    const int bRow = wn * 64 + (lane & 7) + ((lane >> 4) << 3);
    const int bK   = ((lane >> 3) & 1) * 8;

    const uint32_t uAh = smem_u32(sAh), uAl = smem_u32(sAl);
    const uint32_t uWh = smem_u32(sWh), uWl = smem_u32(sWl);

    for (int c = 0; c < DIM / BK; c++) {
        const int k0 = c * BK;
        if (c) __syncthreads();
#pragma unroll
        for (int i = 0; i < 4; i++) {
            const int q = tid + i * 256;     // 0..1023
            const int r = q & 127;
            const int s = q >> 7;            // 0..7 (8 bf16 per seg)
            const size_t goA = (size_t)(m0 + r) * DIM + k0 + s * 8;
            const size_t goW = (size_t)(n0 + r) * DIM + k0 + s * 8;
            *(uint4*)(sAh + r * LDT + s * 8) = *(const uint4*)(Ah + goA);
            *(uint4*)(sAl + r * LDT + s * 8) = *(const uint4*)(Al + goA);
            *(uint4*)(sWh + r * LDT + s * 8) = *(const uint4*)(Wh + goW);
            *(uint4*)(sWl + r * LDT + s * 8) = *(const uint4*)(Wl + goW);
        }
        __syncthreads();

#pragma unroll
        for (int ks = 0; ks < 4; ks++) {
            const int ko = aK + ks * 16;
            uint32_t ah0[4], ah1[4], al0[4], al1[4];
            ldsm4(ah0, uAh + ((aRow)      * LDT + ko) * 2);
            ldsm4(ah1, uAh + ((aRow + 16) * LDT + ko) * 2);
            ldsm4(al0, uAl + ((aRow)      * LDT + ko) * 2);
            ldsm4(al1, uAl + ((aRow + 16) * LDT + ko) * 2);
            const int kb = bK + ks * 16;
#pragma unroll
            for (int np = 0; np < 4; np++) {
                uint32_t bh[4], bl[4];
                ldsm4(bh, uWh + ((bRow + np * 16) * LDT + kb) * 2);
                ldsm4(bl, uWl + ((bRow + np * 16) * LDT + kb) * 2);
                const int n2 = np * 2;
                mma_bf(d[0][n2],     ah0, bh[0], bh[1]);
                mma_bf(d[0][n2 + 1], ah0, bh[2], bh[3]);
                mma_bf(d[1][n2],     ah1, bh[0], bh[1]);
                mma_bf(d[1][n2 + 1], ah1, bh[2], bh[3]);
                mma_bf(d[0][n2],     al0, bh[0], bh[1]);
                mma_bf(d[0][n2 + 1], al0, bh[2], bh[3]);
                mma_bf(d[1][n2],     al1, bh[0], bh[1]);
                mma_bf(d[1][n2 + 1], al1, bh[2], bh[3]);
                mma_bf(d[0][n2],     ah0, bl[0], bl[1]);
                mma_bf(d[0][n2 + 1], ah0, bl[2], bl[3]);
                mma_bf(d[1][n2],     ah1, bl[0], bl[1]);
                mma_bf(d[1][n2 + 1], ah1, bl[2], bl[3]);
            }
        }
    }

    // epilogue
    const int bidx  = m0 / SEQ;                      // CTA fully inside one batch
    const int srow0 = (m0 - bidx * SEQ) + wm * 32 + (lane >> 2);
    const int cbase = n0 + wn * 64;                  // 64-aligned -> single head
    const int ccol  = 2 * (lane & 3);
#pragma unroll
    for (int nt = 0; nt < 8; nt++) {
        const float2 bb = *(const float2*)(bias + cbase + nt * 8 + ccol);
#pragma unroll
        for (int mi = 0; mi < 2; mi++) {
            const int sr = srow0 + mi * 16;
            float2 v0 = make_float2(d[mi][nt][0] + bb.x, d[mi][nt][1] + bb.y);
            float2 v1 = make_float2(d[mi][nt][2] + bb.x, d[mi][nt][3] + bb.y);
            if (SCATTER) {
                const int h   = cbase >> 6;
                const int dof = nt * 8 + ccol;
                const size_t base = ((size_t)bidx * NH + h) * SEQ;
                *(float2*)&C[(base + sr)     * HD + dof] = v0;
                *(float2*)&C[(base + sr + 8) * HD + dof] = v1;
            } else {
                const size_t mrow = (size_t)(m0 + wm * 32 + (lane >> 2) + mi * 16);
                *(float2*)&C[mrow       * DIM + cbase + nt * 8 + ccol] = v0;
                *(float2*)&C[(mrow + 8) * DIM + cbase + nt * 8 + ccol] = v1;
            }
        }
    }
}

__global__ __launch_bounds__(256)
void qkv_mma_kernel(const bf16* __restrict__ xh, const bf16* __restrict__ xl,
                    const bf16* __restrict__ wh, const bf16* __restrict__ wl,
                    const float* __restrict__ bq, const float* __restrict__ bk,
                    const float* __restrict__ bv)
{
    const int z = blockIdx.z;
    const bf16* Wh = wh + (size_t)z * DIM * DIM;
    const bf16* Wl = wl + (size_t)z * DIM * DIM;
    const float* bias = (z == 0) ? bq : (z == 1) ? bk : bv;
    float* C = (z == 0) ? g_q : (z == 1) ? g_k : g_v;
    gemm_mma_body<1>(xh, xl, Wh, Wl, bias, C);
}

__global__ __launch_bounds__(256)
void out_mma_kernel(const bf16* __restrict__ ah, const bf16* __restrict__ al,
                    const bf16* __restrict__ wh, const bf16* __restrict__ wl,
                    const float* __restrict__ bias, float* __restrict__ C)
{
    gemm_mma_body<0>(ah, al, wh + (size_t)3 * DIM * DIM, wl + (size_t)3 * DIM * DIM, bias, C);
}

// ---------------------------------------------------------------------------
// Fused flash-attention with relative position bias (fp32, unchanged from R1).
// ---------------------------------------------------------------------------
__global__ __launch_bounds__(256)
void attn_kernel(const float* __restrict__ rel_emb)
{
    extern __shared__ float sm[];
    float* Qs = sm;
    float* Ks = Qs + 64 * 64;
    float* Vs = Ks + 64 * 64;
    float* Ss = Vs + 64 * HD;
    float* rowm = Ss + 64 * 65;
    float* rowl = rowm + 64;
    float* rowf = rowl + 64;

    const int tid = threadIdx.x;
    const int tx = tid & 15;
    const int ty = tid >> 4;
    const int qt = blockIdx.x;
    const int h  = blockIdx.y;
    const int b  = blockIdx.z;

    const float* Qg    = g_q + (((size_t)b * NH + h) * SEQ + qt * 64) * HD;
    const float* Kbase = g_k + ((size_t)b * NH + h) * SEQ * HD;
    const float* Vbase = g_v + ((size_t)b * NH + h) * SEQ * HD;

#pragma unroll
    for (int i = 0; i < 4; i++) {
        const int f  = tid + i * 256;
        const int r  = f >> 4;
        const int c4 = (f & 15) * 4;
        float4 v = ((const float4*)Qg)[f];
        Qs[(c4 + 0) * 64 + r] = v.x;
        Qs[(c4 + 1) * 64 + r] = v.y;
        Qs[(c4 + 2) * 64 + r] = v.z;
        Qs[(c4 + 3) * 64 + r] = v.w;
    }
    if (tid < 64) { rowm[tid] = -1e30f; rowl[tid] = 0.0f; }

    float acc[4][4];
#pragma unroll
    for (int i = 0; i < 4; i++)
#pragma unroll
        for (int j = 0; j < 4; j++) acc[i][j] = 0.0f;

    for (int kt = 0; kt < SEQ / 64; kt++) {
        const float* Kg = Kbase + (size_t)kt * 64 * HD;
        const float* Vg = Vbase + (size_t)kt * 64 * HD;
        __syncthreads();
#pragma unroll
        for (int i = 0; i < 4; i++) {
            const int f  = tid + i * 256;
            const int r  = f >> 4;
            const int c4 = (f & 15) * 4;
            float4 v = ((const float4*)Kg)[f];
            Ks[(c4 + 0) * 64 + r] = v.x;
            Ks[(c4 + 1) * 64 + r] = v.y;
            Ks[(c4 + 2) * 64 + r] = v.z;
            Ks[(c4 + 3) * 64 + r] = v.w;
            ((float4*)Vs)[f] = ((const float4*)Vg)[f];
        }
        __syncthreads();

        float s[4][4];
#pragma unroll
        for (int i = 0; i < 4; i++)
#pragma unroll
            for (int j = 0; j < 4; j++) s[i][j] = 0.0f;

#pragma unroll 8
        for (int dd = 0; dd < 64; dd++) {
            float4 a  = ((const float4*)(Qs + dd * 64))[ty];
            float4 bb = ((const float4*)(Ks + dd * 64))[tx];
            float af[4] = {a.x, a.y, a.z, a.w};
            float bf[4] = {bb.x, bb.y, bb.z, bb.w};
#pragma unroll
            for (int i = 0; i < 4; i++)
#pragma unroll
                for (int j = 0; j < 4; j++)
                    s[i][j] = fmaf(af[i], bf[j], s[i][j]);
        }
#pragma unroll
        for (int i = 0; i < 4; i++)
#pragma unroll
            for (int j = 0; j < 4; j++)
                Ss[(ty * 4 + i) * 65 + tx * 4 + j] = s[i][j] * 0.125f;
        __syncthreads();

        if (tid < 64) {
            const int r  = tid;
            const int qi = qt * 64 + r;
            float* row = Ss + r * 65;
            const float mo = rowm[r];
            float mn = mo;
            const int kbase = kt * 64;
#pragma unroll
            for (int k2 = 0; k2 < 64; k2++) {
                int dlt = qi - (kbase + k2);
                dlt = max(-MAXD, min(MAXD, dlt));
                float sv = row[k2] + __ldg(&rel_emb[(dlt + MAXD) * NH + h]);
                row[k2] = sv;
                mn = fmaxf(mn, sv);
            }
            const float fac = __expf(mo - mn);
            float ll = rowl[r] * fac;
#pragma unroll
            for (int k2 = 0; k2 < 64; k2++) {
                float p = __expf(row[k2] - mn);
                row[k2] = p;
                ll += p;
            }
            rowm[r] = mn;
            rowl[r] = ll;
            rowf[r] = fac;
        }
        __syncthreads();

#pragma unroll
        for (int i = 0; i < 4; i++) {
            const float fac = rowf[ty * 4 + i];
#pragma unroll
            for (int j = 0; j < 4; j++) acc[i][j] *= fac;
        }
#pragma unroll 8
        for (int k2 = 0; k2 < 64; k2++) {
            float4 v4 = ((const float4*)(Vs + k2 * HD))[tx];
            float vf[4] = {v4.x, v4.y, v4.z, v4.w};
#pragma unroll
            for (int i = 0; i < 4; i++) {
                const float p = Ss[(ty * 4 + i) * 65 + k2];
#pragma unroll
                for (int j = 0; j < 4; j++)
                    acc[i][j] = fmaf(p, vf[j], acc[i][j]);
            }
        }
    }

#pragma unroll
    for (int i = 0; i < 4; i++) {
        const int r  = ty * 4 + i;
        const int qi = qt * 64 + r;
        const float inv = 1.0f / rowl[r];
        float4 v;
        v.x = acc[i][0] * inv;
        v.y = acc[i][1] * inv;
        v.z = acc[i][2] * inv;
        v.w = acc[i][3] * inv;
        *(float4*)&g_att[(((size_t)b * SEQ + qi) * NH + h) * HD + tx * 4] = v;
    }
}

// ---------------------------------------------------------------------------
extern "C" void kernel_launch(void* const* d_in, const int* in_sizes, int n_in,
                              void* d_out, int out_size)
{
    const float* x   = (const float*)d_in[0];
    const float* Wq  = (const float*)d_in[1];
    const float* bq  = (const float*)d_in[2];
    const float* Wk  = (const float*)d_in[3];
    const float* bk  = (const float*)d_in[4];
    const float* Wv  = (const float*)d_in[5];
    const float* bv  = (const float*)d_in[6];
    const float* Wo  = (const float*)d_in[7];
    const float* bo  = (const float*)d_in[8];
    const float* rel = (const float*)d_in[9];
    float* out = (float*)d_out;

    float *att;
    bf16 *xh, *xl, *wh, *wl, *ath, *atl;
    cudaGetSymbolAddress((void**)&att, g_att);
    cudaGetSymbolAddress((void**)&xh,  g_xh);
    cudaGetSymbolAddress((void**)&xl,  g_xl);
    cudaGetSymbolAddress((void**)&wh,  g_wh);
    cudaGetSymbolAddress((void**)&wl,  g_wl);
    cudaGetSymbolAddress((void**)&ath, g_ath);
    cudaGetSymbolAddress((void**)&atl, g_atl);

    // split inputs to bf16 hi/lo
    const int n4x = MTOT * DIM / 4;           // 1048576
    const int n4w = DIM * DIM / 4;            // 262144
    split_kernel<<<n4x / 256, 256>>>(x, xh, xl, n4x);
    split_kernel<<<n4w / 256, 256>>>(Wq, wh + 0 * (size_t)DIM * DIM, wl + 0 * (size_t)DIM * DIM, n4w);
    split_kernel<<<n4w / 256, 256>>>(Wk, wh + 1 * (size_t)DIM * DIM, wl + 1 * (size_t)DIM * DIM, n4w);
    split_kernel<<<n4w / 256, 256>>>(Wv, wh + 2 * (size_t)DIM * DIM, wl + 2 * (size_t)DIM * DIM, n4w);
    split_kernel<<<n4w / 256, 256>>>(Wo, wh + 3 * (size_t)DIM * DIM, wl + 3 * (size_t)DIM * DIM, n4w);

    cudaFuncSetAttribute(qkv_mma_kernel, cudaFuncAttributeMaxDynamicSharedMemorySize, SMEM_GEMM);
    cudaFuncSetAttribute(out_mma_kernel, cudaFuncAttributeMaxDynamicSharedMemorySize, SMEM_GEMM);

    dim3 gq(DIM / BN, MTOT / BM, 3);
    qkv_mma_kernel<<<gq, 256, SMEM_GEMM>>>(xh, xl, wh, wl, bq, bk, bv);

    const size_t smem_attn = (size_t)(64 * 64 * 3 + 64 * 65 + 3 * 64) * sizeof(float);
    cudaFuncSetAttribute(attn_kernel, cudaFuncAttributeMaxDynamicSharedMemorySize, (int)smem_attn);
    dim3 ga(SEQ / 64, NH, BATCH);
    attn_kernel<<<ga, 256, smem_attn>>>(rel);

    split_kernel<<<n4x / 256, 256>>>(att, ath, atl, n4x);

    dim3 go(DIM / BN, MTOT / BM);
    out_mma_kernel<<<go, 256, SMEM_GEMM>>>(ath, atl, wh, wl, bo, out);
}

// round 5
// speedup vs baseline: 3.5319x; 1.7951x over previous
#include <cuda_runtime.h>
#include <cuda_bf16.h>
#include <cstdint>

#define BATCH 2
#define SEQ   2048
#define DIM   1024
#define NH    16
#define HD    64
#define MAXD  128
#define MTOT  (BATCH * SEQ)

typedef __nv_bfloat16 bf16;

// Scratch (static device allocations are allowed)
__device__ bf16 g_xh[MTOT * DIM];
__device__ bf16 g_xl[MTOT * DIM];
__device__ bf16 g_wh[4 * DIM * DIM];
__device__ bf16 g_wl[4 * DIM * DIM];
__device__ bf16 g_qh[MTOT * DIM];
__device__ bf16 g_ql[MTOT * DIM];
__device__ bf16 g_kh[MTOT * DIM];
__device__ bf16 g_kl[MTOT * DIM];
__device__ bf16 g_vh[MTOT * DIM];
__device__ bf16 g_vl[MTOT * DIM];
__device__ bf16 g_ath[MTOT * DIM];
__device__ bf16 g_atl[MTOT * DIM];

// ---------------------------------------------------------------------------
// helpers
// ---------------------------------------------------------------------------
__device__ __forceinline__ uint32_t smem_u32(const void* p) {
    uint32_t a;
    asm("{ .reg .u64 t; cvta.to.shared.u64 t, %1; cvt.u32.u64 %0, t; }" : "=r"(a) : "l"(p));
    return a;
}
__device__ __forceinline__ void ldsm4(uint32_t* r, uint32_t addr) {
    asm volatile("ldmatrix.sync.aligned.m8n8.x4.shared.b16 {%0,%1,%2,%3}, [%4];"
                 : "=r"(r[0]), "=r"(r[1]), "=r"(r[2]), "=r"(r[3]) : "r"(addr));
}
__device__ __forceinline__ void ldsm4t(uint32_t* r, uint32_t addr) {
    asm volatile("ldmatrix.sync.aligned.m8n8.x4.trans.shared.b16 {%0,%1,%2,%3}, [%4];"
                 : "=r"(r[0]), "=r"(r[1]), "=r"(r[2]), "=r"(r[3]) : "r"(addr));
}
__device__ __forceinline__ void mma_bf(float* d, const uint32_t* a, uint32_t b0, uint32_t b1) {
    asm volatile("mma.sync.aligned.m16n8k16.row.col.f32.bf16.bf16.f32 "
                 "{%0,%1,%2,%3}, {%4,%5,%6,%7}, {%8,%9}, {%0,%1,%2,%3};"
                 : "+f"(d[0]), "+f"(d[1]), "+f"(d[2]), "+f"(d[3])
                 : "r"(a[0]), "r"(a[1]), "r"(a[2]), "r"(a[3]), "r"(b0), "r"(b1));
}
__device__ __forceinline__ uint32_t pack_bf2(bf16 a, bf16 b) {
    __nv_bfloat162 t(a, b);
    return *reinterpret_cast<uint32_t*>(&t);
}
__device__ __forceinline__ void split2(float2 v, uint32_t& hi, uint32_t& lo) {
    bf16 h0 = __float2bfloat16_rn(v.x);
    bf16 l0 = __float2bfloat16_rn(v.x - __bfloat162float(h0));
    bf16 h1 = __float2bfloat16_rn(v.y);
    bf16 l1 = __float2bfloat16_rn(v.y - __bfloat162float(h1));
    hi = pack_bf2(h0, h1);
    lo = pack_bf2(l0, l1);
}

// ---------------------------------------------------------------------------
// split fp32 -> bf16 hi/lo (x and weights, one-time)
// ---------------------------------------------------------------------------
__global__ __launch_bounds__(256)
void split_kernel(const float* __restrict__ in, bf16* __restrict__ hi,
                  bf16* __restrict__ lo, int n4)
{
    int i = blockIdx.x * blockDim.x + threadIdx.x;
    if (i >= n4) return;
    float4 v = ((const float4*)in)[i];
    uint32_t h0, l0, h1, l1;
    split2(make_float2(v.x, v.y), h0, l0);
    split2(make_float2(v.z, v.w), h1, l1);
    ((uint2*)hi)[i] = make_uint2(h0, h1);
    ((uint2*)lo)[i] = make_uint2(l0, l1);
}

// ---------------------------------------------------------------------------
// HMMA split-bf16 GEMM: C = A[M,1024] @ W[N,1024]^T + bias
// 128x128x64 tile, 8 warps (4M x 2N), warp does 32x64 via m16n8k16.
// SCATTER=1: write bf16 hi/lo pairs in [B,H,S,Hd] layout.
// SCATTER=0: write fp32 row-major [M,DIM].
// ---------------------------------------------------------------------------
#define BM 128
#define BN 128
#define BK 64
#define LDT 72
#define SMEM_GEMM (4 * BM * LDT * 2)

template <int SCATTER>
__device__ __forceinline__ void gemm_mma_body(
    const bf16* __restrict__ Ah, const bf16* __restrict__ Al,
    const bf16* __restrict__ Wh, const bf16* __restrict__ Wl,
    const float* __restrict__ bias, float* __restrict__ C,
    bf16* __restrict__ Ch, bf16* __restrict__ Cl)
{
    extern __shared__ __align__(16) char smem[];
    bf16* sAh = (bf16*)smem;
    bf16* sAl = sAh + BM * LDT;
    bf16* sWh = sAl + BM * LDT;
    bf16* sWl = sWh + BN * LDT;

    const int tid  = threadIdx.x;
    const int lane = tid & 31;
    const int wid  = tid >> 5;
    const int wm   = wid & 3;
    const int wn   = wid >> 2;
    const int m0   = blockIdx.y * BM;
    const int n0   = blockIdx.x * BN;

    float d[2][8][4];
#pragma unroll
    for (int i = 0; i < 2; i++)
#pragma unroll
        for (int j = 0; j < 8; j++)
#pragma unroll
            for (int t = 0; t < 4; t++) d[i][j][t] = 0.0f;

    const int aRow = wm * 32 + (lane & 15);
    const int aK   = (lane >> 4) * 8;
    const int bRow = wn * 64 + (lane & 7) + ((lane >> 4) << 3);
    const int bK   = ((lane >> 3) & 1) * 8;

    const uint32_t uAh = smem_u32(sAh), uAl = smem_u32(sAl);
    const uint32_t uWh = smem_u32(sWh), uWl = smem_u32(sWl);

    for (int c = 0; c < DIM / BK; c++) {
        const int k0 = c * BK;
        if (c) __syncthreads();
#pragma unroll
        for (int i = 0; i < 4; i++) {
            const int q = tid + i * 256;
            const int r = q & 127;
            const int s = q >> 7;
            const size_t goA = (size_t)(m0 + r) * DIM + k0 + s * 8;
            const size_t goW = (size_t)(n0 + r) * DIM + k0 + s * 8;
            *(uint4*)(sAh + r * LDT + s * 8) = *(const uint4*)(Ah + goA);
            *(uint4*)(sAl + r * LDT + s * 8) = *(const uint4*)(Al + goA);
            *(uint4*)(sWh + r * LDT + s * 8) = *(const uint4*)(Wh + goW);
            *(uint4*)(sWl + r * LDT + s * 8) = *(const uint4*)(Wl + goW);
        }
        __syncthreads();

#pragma unroll
        for (int ks = 0; ks < 4; ks++) {
            const int ko = aK + ks * 16;
            uint32_t ah0[4], ah1[4], al0[4], al1[4];
            ldsm4(ah0, uAh + ((aRow)      * LDT + ko) * 2);
            ldsm4(ah1, uAh + ((aRow + 16) * LDT + ko) * 2);
            ldsm4(al0, uAl + ((aRow)      * LDT + ko) * 2);
            ldsm4(al1, uAl + ((aRow + 16) * LDT + ko) * 2);
            const int kb = bK + ks * 16;
#pragma unroll
            for (int np = 0; np < 4; np++) {
                uint32_t bh[4], bl[4];
                ldsm4(bh, uWh + ((bRow + np * 16) * LDT + kb) * 2);
                ldsm4(bl, uWl + ((bRow + np * 16) * LDT + kb) * 2);
                const int n2 = np * 2;
                mma_bf(d[0][n2],     ah0, bh[0], bh[1]);
                mma_bf(d[0][n2 + 1], ah0, bh[2], bh[3]);
                mma_bf(d[1][n2],     ah1, bh[0], bh[1]);
                mma_bf(d[1][n2 + 1], ah1, bh[2], bh[3]);
                mma_bf(d[0][n2],     al0, bh[0], bh[1]);
                mma_bf(d[0][n2 + 1], al0, bh[2], bh[3]);
                mma_bf(d[1][n2],     al1, bh[0], bh[1]);
                mma_bf(d[1][n2 + 1], al1, bh[2], bh[3]);
                mma_bf(d[0][n2],     ah0, bl[0], bl[1]);
                mma_bf(d[0][n2 + 1], ah0, bl[2], bl[3]);
                mma_bf(d[1][n2],     ah1, bl[0], bl[1]);
                mma_bf(d[1][n2 + 1], ah1, bl[2], bl[3]);
            }
        }
    }

    const int bidx  = m0 / SEQ;
    const int srow0 = (m0 - bidx * SEQ) + wm * 32 + (lane >> 2);
    const int cbase = n0 + wn * 64;
    const int ccol  = 2 * (lane & 3);
#pragma unroll
    for (int nt = 0; nt < 8; nt++) {
        const float2 bb = *(const float2*)(bias + cbase + nt * 8 + ccol);
#pragma unroll
        for (int mi = 0; mi < 2; mi++) {
            const int sr = srow0 + mi * 16;
            float2 v0 = make_float2(d[mi][nt][0] + bb.x, d[mi][nt][1] + bb.y);
            float2 v1 = make_float2(d[mi][nt][2] + bb.x, d[mi][nt][3] + bb.y);
            if (SCATTER) {
                const int h   = cbase >> 6;
                const int dof = nt * 8 + ccol;
                const size_t base = ((size_t)bidx * NH + h) * SEQ;
                uint32_t hi, lo;
                split2(v0, hi, lo);
                *(uint32_t*)&Ch[(base + sr) * HD + dof] = hi;
                *(uint32_t*)&Cl[(base + sr) * HD + dof] = lo;
                split2(v1, hi, lo);
                *(uint32_t*)&Ch[(base + sr + 8) * HD + dof] = hi;
                *(uint32_t*)&Cl[(base + sr + 8) * HD + dof] = lo;
            } else {
                const size_t mrow = (size_t)(m0 + wm * 32 + (lane >> 2) + mi * 16);
                *(float2*)&C[mrow       * DIM + cbase + nt * 8 + ccol] = v0;
                *(float2*)&C[(mrow + 8) * DIM + cbase + nt * 8 + ccol] = v1;
            }
        }
    }
}

__global__ __launch_bounds__(256)
void qkv_mma_kernel(const bf16* __restrict__ xh, const bf16* __restrict__ xl,
                    const bf16* __restrict__ wh, const bf16* __restrict__ wl,
                    const float* __restrict__ bq, const float* __restrict__ bk,
                    const float* __restrict__ bv)
{
    const int z = blockIdx.z;
    const bf16* Wh = wh + (size_t)z * DIM * DIM;
    const bf16* Wl = wl + (size_t)z * DIM * DIM;
    const float* bias = (z == 0) ? bq : (z == 1) ? bk : bv;
    bf16* Ch = (z == 0) ? g_qh : (z == 1) ? g_kh : g_vh;
    bf16* Cl = (z == 0) ? g_ql : (z == 1) ? g_kl : g_vl;
    gemm_mma_body<1>(xh, xl, Wh, Wl, bias, nullptr, Ch, Cl);
}

__global__ __launch_bounds__(256)
void out_mma_kernel(const bf16* __restrict__ ah, const bf16* __restrict__ al,
                    const bf16* __restrict__ wh, const bf16* __restrict__ wl,
                    const float* __restrict__ bias, float* __restrict__ C)
{
    gemm_mma_body<0>(ah, al, wh + (size_t)3 * DIM * DIM, wl + (size_t)3 * DIM * DIM,
                     bias, C, nullptr, nullptr);
}

// ---------------------------------------------------------------------------
// HMMA flash-attention with relative position bias.
// CTA: 64-query tile x (head, batch). 8 warps: 2M x 4N over the 64x64 tile.
// QK^T and P@V via m16n8k16 bf16 with 3-term split. Softmax fp32 in smem.
// ---------------------------------------------------------------------------
#define ALDT 72
#define SLDT 68
#define SMEM_ATTN (8 * 64 * ALDT * 2 + 64 * SLDT * 4 + 3 * 64 * 4)

__global__ __launch_bounds__(256, 2)
void attn_mma_kernel(const float* __restrict__ rel_emb)
{
    extern __shared__ __align__(16) char smem[];
    bf16* sQh = (bf16*)smem;
    bf16* sQl = sQh + 64 * ALDT;
    bf16* sKh = sQl + 64 * ALDT;
    bf16* sKl = sKh + 64 * ALDT;
    bf16* sVh = sKl + 64 * ALDT;
    bf16* sVl = sVh + 64 * ALDT;
    bf16* sPh = sVl + 64 * ALDT;
    bf16* sPl = sPh + 64 * ALDT;
    float* sS   = (float*)(sPl + 64 * ALDT);
    float* rowm = sS + 64 * SLDT;
    float* rowl = rowm + 64;
    float* rowf = rowl + 64;

    const int tid  = threadIdx.x;
    const int lane = tid & 31;
    const int wid  = tid >> 5;
    const int wm   = wid & 1;
    const int wn   = wid >> 1;
    const int qt = blockIdx.x, h = blockIdx.y, b = blockIdx.z;
    const size_t bhb = ((size_t)b * NH + h) * SEQ;

    const bf16* Qhp = g_qh + (bhb + qt * 64) * HD;
    const bf16* Qlp = g_ql + (bhb + qt * 64) * HD;

#pragma unroll
    for (int i = 0; i < 2; i++) {
        const int f = tid + i * 256, r = f >> 3, s = f & 7;
        *(uint4*)(sQh + r * ALDT + s * 8) = *(const uint4*)(Qhp + r * HD + s * 8);
        *(uint4*)(sQl + r * ALDT + s * 8) = *(const uint4*)(Qlp + r * HD + s * 8);
    }
    if (tid < 64) { rowm[tid] = -1e30f; rowl[tid] = 0.0f; }

    const uint32_t uQh = smem_u32(sQh), uQl = smem_u32(sQl);
    const uint32_t uKh = smem_u32(sKh), uKl = smem_u32(sKl);
    const uint32_t uVh = smem_u32(sVh), uVl = smem_u32(sVl);
    const uint32_t uPh = smem_u32(sPh), uPl = smem_u32(sPl);

    const int aRow  = wm * 32 + (lane & 15);
    const int aK    = ((lane >> 4) & 1) * 8;
    const int bRow  = wn * 16 + (lane & 7) + ((lane >> 4) & 1) * 8;
    const int bK    = ((lane >> 3) & 1) * 8;
    const int vRowK = (lane & 7) + ((lane >> 3) & 1) * 8;
    const int vColD = wn * 16 + ((lane >> 4) & 1) * 8;

    float o[2][2][4];
#pragma unroll
    for (int mi = 0; mi < 2; mi++)
#pragma unroll
        for (int ni = 0; ni < 2; ni++)
#pragma unroll
            for (int t = 0; t < 4; t++) o[mi][ni][t] = 0.0f;

    for (int kt = 0; kt < SEQ / 64; kt++) {
        __syncthreads();
        const bf16* Khp = g_kh + (bhb + kt * 64) * HD;
        const bf16* Klp = g_kl + (bhb + kt * 64) * HD;
        const bf16* Vhp = g_vh + (bhb + kt * 64) * HD;
        const bf16* Vlp = g_vl + (bhb + kt * 64) * HD;
#pragma unroll
        for (int i = 0; i < 2; i++) {
            const int f = tid + i * 256, r = f >> 3, s = f & 7;
            *(uint4*)(sKh + r * ALDT + s * 8) = *(const uint4*)(Khp + r * HD + s * 8);
            *(uint4*)(sKl + r * ALDT + s * 8) = *(const uint4*)(Klp + r * HD + s * 8);
            *(uint4*)(sVh + r * ALDT + s * 8) = *(const uint4*)(Vhp + r * HD + s * 8);
            *(uint4*)(sVl + r * ALDT + s * 8) = *(const uint4*)(Vlp + r * HD + s * 8);
        }
        __syncthreads();

        // ---- QK^T (split-bf16, 3 terms) ----
        float sf[2][2][4];
#pragma unroll
        for (int mi = 0; mi < 2; mi++)
#pragma unroll
            for (int ni = 0; ni < 2; ni++)
#pragma unroll
                for (int t = 0; t < 4; t++) sf[mi][ni][t] = 0.0f;

#pragma unroll
        for (int ks = 0; ks < 4; ks++) {
            uint32_t qh0[4], qh1[4], ql0[4], ql1[4], kh[4], kl[4];
            const int ko = ks * 16 + aK;
            ldsm4(qh0, uQh + ((aRow)      * ALDT + ko) * 2);
            ldsm4(qh1, uQh + ((aRow + 16) * ALDT + ko) * 2);
            ldsm4(ql0, uQl + ((aRow)      * ALDT + ko) * 2);
            ldsm4(ql1, uQl + ((aRow + 16) * ALDT + ko) * 2);
            const int kb = ks * 16 + bK;
            ldsm4(kh, uKh + (bRow * ALDT + kb) * 2);
            ldsm4(kl, uKl + (bRow * ALDT + kb) * 2);
#pragma unroll
            for (int ni = 0; ni < 2; ni++) {
                mma_bf(sf[0][ni], qh0, kh[2 * ni], kh[2 * ni + 1]);
                mma_bf(sf[1][ni], qh1, kh[2 * ni], kh[2 * ni + 1]);
                mma_bf(sf[0][ni], ql0, kh[2 * ni], kh[2 * ni + 1]);
                mma_bf(sf[1][ni], ql1, kh[2 * ni], kh[2 * ni + 1]);
                mma_bf(sf[0][ni], qh0, kl[2 * ni], kl[2 * ni + 1]);
                mma_bf(sf[1][ni], qh1, kl[2 * ni], kl[2 * ni + 1]);
            }
        }
        {
            const int r0 = wm * 32 + (lane >> 2);
            const int c0 = wn * 16 + 2 * (lane & 3);
#pragma unroll
            for (int mi = 0; mi < 2; mi++)
#pragma unroll
                for (int ni = 0; ni < 2; ni++) {
                    const int rr = r0 + mi * 16, cc = c0 + ni * 8;
                    *(float2*)&sS[rr * SLDT + cc] =
                        make_float2(sf[mi][ni][0] * 0.125f, sf[mi][ni][1] * 0.125f);
                    *(float2*)&sS[(rr + 8) * SLDT + cc] =
                        make_float2(sf[mi][ni][2] * 0.125f, sf[mi][ni][3] * 0.125f);
                }
        }
        __syncthreads();

        // ---- online softmax: 4 threads per row ----
        {
            const int sr = tid >> 2, sq = tid & 3;
            const int cb = sq * 16;
            const int qi = qt * 64 + sr;
            float v[16], mx = -1e30f;
#pragma unroll
            for (int j = 0; j < 4; j++) {
                float4 t = *(float4*)&sS[sr * SLDT + cb + j * 4];
                float tv[4] = {t.x, t.y, t.z, t.w};
#pragma unroll
                for (int e = 0; e < 4; e++) {
                    const int kj = kt * 64 + cb + j * 4 + e;
                    int dlt = qi - kj;
                    dlt = max(-MAXD, min(MAXD, dlt));
                    const float sv = tv[e] + __ldg(rel_emb + (dlt + MAXD) * NH + h);
                    v[j * 4 + e] = sv;
                    mx = fmaxf(mx, sv);
                }
            }
            mx = fmaxf(mx, __shfl_xor_sync(0xFFFFFFFFu, mx, 1));
            mx = fmaxf(mx, __shfl_xor_sync(0xFFFFFFFFu, mx, 2));
            const float mo = rowm[sr];
            const float mn = fmaxf(mo, mx);
            float sum = 0.0f;
#pragma unroll
            for (int j2 = 0; j2 < 8; j2++) {
                const float p0 = __expf(v[2 * j2]     - mn);
                const float p1 = __expf(v[2 * j2 + 1] - mn);
                sum += p0 + p1;
                uint32_t hi, lo;
                split2(make_float2(p0, p1), hi, lo);
                *(uint32_t*)(sPh + sr * ALDT + cb + 2 * j2) = hi;
                *(uint32_t*)(sPl + sr * ALDT + cb + 2 * j2) = lo;
            }
            sum += __shfl_xor_sync(0xFFFFFFFFu, sum, 1);
            sum += __shfl_xor_sync(0xFFFFFFFFu, sum, 2);
            if (sq == 0) {
                const float fac = __expf(mo - mn);
                rowf[sr] = fac;
                rowm[sr] = mn;
                rowl[sr] = rowl[sr] * fac + sum;
            }
        }
        __syncthreads();

        // ---- rescale O, then P@V (split-bf16, 3 terms) ----
        {
            const int rr = wm * 32 + (lane >> 2);
            const float f00 = rowf[rr], f01 = rowf[rr + 8];
            const float f10 = rowf[rr + 16], f11 = rowf[rr + 24];
#pragma unroll
            for (int ni = 0; ni < 2; ni++) {
                o[0][ni][0] *= f00; o[0][ni][1] *= f00;
                o[0][ni][2] *= f01; o[0][ni][3] *= f01;
                o[1][ni][0] *= f10; o[1][ni][1] *= f10;
                o[1][ni][2] *= f11; o[1][ni][3] *= f11;
            }
        }
#pragma unroll
        for (int ks = 0; ks < 4; ks++) {
            uint32_t ph0[4], ph1[4], pl0[4], pl1[4], vh[4], vl[4];
            const int ko = ks * 16 + aK;
            ldsm4(ph0, uPh + ((aRow)      * ALDT + ko) * 2);
            ldsm4(ph1, uPh + ((aRow + 16) * ALDT + ko) * 2);
            ldsm4(pl0, uPl + ((aRow)      * ALDT + ko) * 2);
            ldsm4(pl1, uPl + ((aRow + 16) * ALDT + ko) * 2);
            const int kr = ks * 16 + vRowK;
            ldsm4t(vh, uVh + (kr * ALDT + vColD) * 2);
            ldsm4t(vl, uVl + (kr * ALDT + vColD) * 2);
#pragma unroll
            for (int ni = 0; ni < 2; ni++) {
                mma_bf(o[0][ni], ph0, vh[2 * ni], vh[2 * ni + 1]);
                mma_bf(o[1][ni], ph1, vh[2 * ni], vh[2 * ni + 1]);
                mma_bf(o[0][ni], pl0, vh[2 * ni], vh[2 * ni + 1]);
                mma_bf(o[1][ni], pl1, vh[2 * ni], vh[2 * ni + 1]);
                mma_bf(o[0][ni], ph0, vl[2 * ni], vl[2 * ni + 1]);
                mma_bf(o[1][ni], ph1, vl[2 * ni], vl[2 * ni + 1]);
            }
        }
    }

    // ---- epilogue: normalize, split to bf16 hi/lo, write [B,S,H*Hd] ----
    {
        const int rr = wm * 32 + (lane >> 2);
        const float i00 = 1.0f / rowl[rr],      i01 = 1.0f / rowl[rr + 8];
        const float i10 = 1.0f / rowl[rr + 16], i11 = 1.0f / rowl[rr + 24];
        const int c0 = wn * 16 + 2 * (lane & 3);
#pragma unroll
        for (int mi = 0; mi < 2; mi++)
#pragma unroll
            for (int ni = 0; ni < 2; ni++) {
                const float iv0 = mi ? i10 : i00;
                const float iv1 = mi ? i11 : i01;
                const int row0 = qt * 64 + wm * 32 + mi * 16 + (lane >> 2);
                const int col  = h * HD + c0 + ni * 8;
                const size_t a0 = ((size_t)b * SEQ + row0)     * DIM + col;
                const size_t a1 = ((size_t)b * SEQ + row0 + 8) * DIM + col;
                uint32_t hi, lo;
                split2(make_float2(o[mi][ni][0] * iv0, o[mi][ni][1] * iv0), hi, lo);
                *(uint32_t*)(g_ath + a0) = hi;
                *(uint32_t*)(g_atl + a0) = lo;
                split2(make_float2(o[mi][ni][2] * iv1, o[mi][ni][3] * iv1), hi, lo);
                *(uint32_t*)(g_ath + a1) = hi;
                *(uint32_t*)(g_atl + a1) = lo;
            }
    }
}

// ---------------------------------------------------------------------------
extern "C" void kernel_launch(void* const* d_in, const int* in_sizes, int n_in,
                              void* d_out, int out_size)
{
    const float* x   = (const float*)d_in[0];
    const float* Wq  = (const float*)d_in[1];
    const float* bq  = (const float*)d_in[2];
    const float* Wk  = (const float*)d_in[3];
    const float* bk  = (const float*)d_in[4];
    const float* Wv  = (const float*)d_in[5];
    const float* bv  = (const float*)d_in[6];
    const float* Wo  = (const float*)d_in[7];
    const float* bo  = (const float*)d_in[8];
    const float* rel = (const float*)d_in[9];
    float* out = (float*)d_out;

    bf16 *xh, *xl, *wh, *wl, *ath, *atl;
    cudaGetSymbolAddress((void**)&xh,  g_xh);
    cudaGetSymbolAddress((void**)&xl,  g_xl);
    cudaGetSymbolAddress((void**)&wh,  g_wh);
    cudaGetSymbolAddress((void**)&wl,  g_wl);
    cudaGetSymbolAddress((void**)&ath, g_ath);
    cudaGetSymbolAddress((void**)&atl, g_atl);

    const int n4x = MTOT * DIM / 4;
    const int n4w = DIM * DIM / 4;
    split_kernel<<<n4x / 256, 256>>>(x, xh, xl, n4x);
    split_kernel<<<n4w / 256, 256>>>(Wq, wh + 0 * (size_t)DIM * DIM, wl + 0 * (size_t)DIM * DIM, n4w);
    split_kernel<<<n4w / 256, 256>>>(Wk, wh + 1 * (size_t)DIM * DIM, wl + 1 * (size_t)DIM * DIM, n4w);
    split_kernel<<<n4w / 256, 256>>>(Wv, wh + 2 * (size_t)DIM * DIM, wl + 2 * (size_t)DIM * DIM, n4w);
    split_kernel<<<n4w / 256, 256>>>(Wo, wh + 3 * (size_t)DIM * DIM, wl + 3 * (size_t)DIM * DIM, n4w);

    cudaFuncSetAttribute(qkv_mma_kernel, cudaFuncAttributeMaxDynamicSharedMemorySize, SMEM_GEMM);
    cudaFuncSetAttribute(out_mma_kernel, cudaFuncAttributeMaxDynamicSharedMemorySize, SMEM_GEMM);
    cudaFuncSetAttribute(attn_mma_kernel, cudaFuncAttributeMaxDynamicSharedMemorySize, SMEM_ATTN);

    dim3 gq(DIM / BN, MTOT / BM, 3);
    qkv_mma_kernel<<<gq, 256, SMEM_GEMM>>>(xh, xl, wh, wl, bq, bk, bv);

    dim3 ga(SEQ / 64, NH, BATCH);
    attn_mma_kernel<<<ga, 256, SMEM_ATTN>>>(rel);

    dim3 go(DIM / BN, MTOT / BM);
    out_mma_kernel<<<go, 256, SMEM_GEMM>>>(ath, atl, wh, wl, bo, out);
}

// round 7
// speedup vs baseline: 4.6582x; 1.3189x over previous
#include <cuda_runtime.h>
#include <cuda_bf16.h>
#include <cstdint>

#define BATCH 2
#define SEQ   2048
#define DIM   1024
#define NH    16
#define HD    64
#define MAXD  128
#define MTOT  (BATCH * SEQ)

typedef __nv_bfloat16 bf16;

// Scratch (static device allocations are allowed)
__device__ bf16 g_xh[MTOT * DIM];
__device__ bf16 g_xl[MTOT * DIM];
__device__ bf16 g_wh[4 * DIM * DIM];
__device__ bf16 g_wl[4 * DIM * DIM];
__device__ bf16 g_qh[MTOT * DIM];
__device__ bf16 g_ql[MTOT * DIM];
__device__ bf16 g_kh[MTOT * DIM];
__device__ bf16 g_kl[MTOT * DIM];
__device__ bf16 g_vh[MTOT * DIM];
__device__ bf16 g_vl[MTOT * DIM];
__device__ bf16 g_ath[MTOT * DIM];
__device__ bf16 g_atl[MTOT * DIM];

// ---------------------------------------------------------------------------
// helpers
// ---------------------------------------------------------------------------
__device__ __forceinline__ uint32_t smem_u32(const void* p) {
    uint32_t a;
    asm("{ .reg .u64 t; cvta.to.shared.u64 t, %1; cvt.u32.u64 %0, t; }" : "=r"(a) : "l"(p));
    return a;
}
__device__ __forceinline__ void ldsm4(uint32_t* r, uint32_t addr) {
    asm volatile("ldmatrix.sync.aligned.m8n8.x4.shared.b16 {%0,%1,%2,%3}, [%4];"
                 : "=r"(r[0]), "=r"(r[1]), "=r"(r[2]), "=r"(r[3]) : "r"(addr));
}
__device__ __forceinline__ void ldsm4t(uint32_t* r, uint32_t addr) {
    asm volatile("ldmatrix.sync.aligned.m8n8.x4.trans.shared.b16 {%0,%1,%2,%3}, [%4];"
                 : "=r"(r[0]), "=r"(r[1]), "=r"(r[2]), "=r"(r[3]) : "r"(addr));
}
__device__ __forceinline__ void mma_bf(float* d, const uint32_t* a, uint32_t b0, uint32_t b1) {
    asm volatile("mma.sync.aligned.m16n8k16.row.col.f32.bf16.bf16.f32 "
                 "{%0,%1,%2,%3}, {%4,%5,%6,%7}, {%8,%9}, {%0,%1,%2,%3};"
                 : "+f"(d[0]), "+f"(d[1]), "+f"(d[2]), "+f"(d[3])
                 : "r"(a[0]), "r"(a[1]), "r"(a[2]), "r"(a[3]), "r"(b0), "r"(b1));
}
__device__ __forceinline__ void cpa16(uint32_t dst, const void* src) {
    asm volatile("cp.async.cg.shared.global [%0], [%1], 16;" :: "r"(dst), "l"(src));
}
#define CPA_COMMIT() asm volatile("cp.async.commit_group;" ::: "memory")
#define CPA_WAIT(n)  asm volatile("cp.async.wait_group %0;" :: "n"(n) : "memory")

__device__ __forceinline__ uint32_t pack_bf2(bf16 a, bf16 b) {
    __nv_bfloat162 t(a, b);
    return *reinterpret_cast<uint32_t*>(&t);
}
__device__ __forceinline__ void split2(float2 v, uint32_t& hi, uint32_t& lo) {
    bf16 h0 = __float2bfloat16_rn(v.x);
    bf16 l0 = __float2bfloat16_rn(v.x - __bfloat162float(h0));
    bf16 h1 = __float2bfloat16_rn(v.y);
    bf16 l1 = __float2bfloat16_rn(v.y - __bfloat162float(h1));
    hi = pack_bf2(h0, h1);
    lo = pack_bf2(l0, l1);
}

// ---------------------------------------------------------------------------
// one-shot split of x + 4 weights -> bf16 hi/lo
// ---------------------------------------------------------------------------
__global__ __launch_bounds__(256)
void split_all_kernel(const float* __restrict__ x,
                      const float* __restrict__ Wq, const float* __restrict__ Wk,
                      const float* __restrict__ Wv, const float* __restrict__ Wo)
{
    const int bid = blockIdx.x;
    const float* in;
    bf16 *hi, *lo;
    int i;
    if (bid < 4096) {                      // x: 4096 blocks
        in = x; hi = g_xh; lo = g_xl;
        i = bid * 256 + threadIdx.x;
    } else {                               // weights: 1024 blocks each
        const int z  = (bid - 4096) >> 10;
        const int lb = (bid - 4096) & 1023;
        in = (z == 0) ? Wq : (z == 1) ? Wk : (z == 2) ? Wv : Wo;
        hi = g_wh + (size_t)z * DIM * DIM;
        lo = g_wl + (size_t)z * DIM * DIM;
        i = lb * 256 + threadIdx.x;
    }
    float4 v = ((const float4*)in)[i];
    uint32_t h0, l0, h1, l1;
    split2(make_float2(v.x, v.y), h0, l0);
    split2(make_float2(v.z, v.w), h1, l1);
    ((uint2*)hi)[i] = make_uint2(h0, h1);
    ((uint2*)lo)[i] = make_uint2(l0, l1);
}

// ---------------------------------------------------------------------------
// HMMA split-bf16 GEMM with 2-stage cp.async pipeline.
// C = A[M,1024] @ W[N,1024]^T + bias.  128x128 tile, BK=32, 8 warps (4M x 2N).
// ---------------------------------------------------------------------------
#define BK2  32
#define LDT2 40                         // padded row stride (bf16): conflict-free ldsm
#define TSTRIDE (128 * LDT2)            // bf16 elements per tensor per stage
#define STG  (4 * TSTRIDE)              // bf16 elements per stage
#define SMEM_GEMM (2 * STG * 2)         // 81920 bytes

template <int SCATTER>
__device__ __forceinline__ void gemm_mma_body(
    const bf16* __restrict__ Ah, const bf16* __restrict__ Al,
    const bf16* __restrict__ Wh, const bf16* __restrict__ Wl,
    const float* __restrict__ bias, float* __restrict__ C,
    bf16* __restrict__ Ch, bf16* __restrict__ Cl)
{
    extern __shared__ __align__(16) char smem_raw[];
    bf16* smem = (bf16*)smem_raw;

    const int tid  = threadIdx.x;
    const int lane = tid & 31;
    const int wid  = tid >> 5;
    const int wm   = wid & 3;
    const int wn   = wid >> 2;
    const int m0   = blockIdx.y * 128;
    const int n0   = blockIdx.x * 128;

    float d[2][8][4];
#pragma unroll
    for (int i = 0; i < 2; i++)
#pragma unroll
        for (int j = 0; j < 8; j++)
#pragma unroll
            for (int t = 0; t < 4; t++) d[i][j][t] = 0.0f;

    const int aRow = wm * 32 + (lane & 15);
    const int aK   = (lane >> 4) * 8;
    const int bRow = wn * 64 + (lane & 7) + ((lane >> 4) << 3);
    const int bK   = ((lane >> 3) & 1) * 8;

    const uint32_t sb = smem_u32(smem);

    auto issue_stage = [&](int c, int st) {
        const int k0 = c * BK2;
        const uint32_t ub = sb + (uint32_t)(st * STG) * 2;
#pragma unroll
        for (int i = 0; i < 2; i++) {
            const int f = tid + i * 256;
            const int r = f >> 2;
            const int s = (f & 3) * 8;
            const size_t goA = (size_t)(m0 + r) * DIM + k0 + s;
            const size_t goW = (size_t)(n0 + r) * DIM + k0 + s;
            const uint32_t so = (uint32_t)(r * LDT2 + s) * 2;
            cpa16(ub + 0 * TSTRIDE * 2 + so, Ah + goA);
            cpa16(ub + 1 * TSTRIDE * 2 + so, Al + goA);
            cpa16(ub + 2 * TSTRIDE * 2 + so, Wh + goW);
            cpa16(ub + 3 * TSTRIDE * 2 + so, Wl + goW);
        }
        CPA_COMMIT();
    };

    issue_stage(0, 0);
    for (int c = 0; c < DIM / BK2; c++) {
        const int st = c & 1;
        if (c + 1 < DIM / BK2) { issue_stage(c + 1, st ^ 1); CPA_WAIT(1); }
        else                   { CPA_WAIT(0); }
        __syncthreads();

        const uint32_t ub  = sb + (uint32_t)(st * STG) * 2;
        const uint32_t uAh = ub;
        const uint32_t uAl = ub + 1 * TSTRIDE * 2;
        const uint32_t uWh = ub + 2 * TSTRIDE * 2;
        const uint32_t uWl = ub + 3 * TSTRIDE * 2;

#pragma unroll
        for (int ks = 0; ks < 2; ks++) {
            const int ko = aK + ks * 16;
            uint32_t ah0[4], ah1[4], al0[4], al1[4];
            ldsm4(ah0, uAh + ((aRow)      * LDT2 + ko) * 2);
            ldsm4(ah1, uAh + ((aRow + 16) * LDT2 + ko) * 2);
            ldsm4(al0, uAl + ((aRow)      * LDT2 + ko) * 2);
            ldsm4(al1, uAl + ((aRow + 16) * LDT2 + ko) * 2);
            const int kb = bK + ks * 16;
#pragma unroll
            for (int np = 0; np < 4; np++) {
                uint32_t bh[4], bl[4];
                ldsm4(bh, uWh + ((bRow + np * 16) * LDT2 + kb) * 2);
                ldsm4(bl, uWl + ((bRow + np * 16) * LDT2 + kb) * 2);
                const int n2 = np * 2;
                mma_bf(d[0][n2],     ah0, bh[0], bh[1]);
                mma_bf(d[0][n2 + 1], ah0, bh[2], bh[3]);
                mma_bf(d[1][n2],     ah1, bh[0], bh[1]);
                mma_bf(d[1][n2 + 1], ah1, bh[2], bh[3]);
                mma_bf(d[0][n2],     al0, bh[0], bh[1]);
                mma_bf(d[0][n2 + 1], al0, bh[2], bh[3]);
                mma_bf(d[1][n2],     al1, bh[0], bh[1]);
                mma_bf(d[1][n2 + 1], al1, bh[2], bh[3]);
                mma_bf(d[0][n2],     ah0, bl[0], bl[1]);
                mma_bf(d[0][n2 + 1], ah0, bl[2], bl[3]);
                mma_bf(d[1][n2],     ah1, bl[0], bl[1]);
                mma_bf(d[1][n2 + 1], ah1, bl[2], bl[3]);
            }
        }
        __syncthreads();
    }

    const int bidx  = m0 / SEQ;
    const int srow0 = (m0 - bidx * SEQ) + wm * 32 + (lane >> 2);
    const int cbase = n0 + wn * 64;
    const int ccol  = 2 * (lane & 3);
#pragma unroll
    for (int nt = 0; nt < 8; nt++) {
        const float2 bb = *(const float2*)(bias + cbase + nt * 8 + ccol);
#pragma unroll
        for (int mi = 0; mi < 2; mi++) {
            const int sr = srow0 + mi * 16;
            float2 v0 = make_float2(d[mi][nt][0] + bb.x, d[mi][nt][1] + bb.y);
            float2 v1 = make_float2(d[mi][nt][2] + bb.x, d[mi][nt][3] + bb.y);
            if (SCATTER) {
                const int h   = cbase >> 6;
                const int dof = nt * 8 + ccol;
                const size_t base = ((size_t)bidx * NH + h) * SEQ;
                uint32_t hi, lo;
                split2(v0, hi, lo);
                *(uint32_t*)&Ch[(base + sr) * HD + dof] = hi;
                *(uint32_t*)&Cl[(base + sr) * HD + dof] = lo;
                split2(v1, hi, lo);
                *(uint32_t*)&Ch[(base + sr + 8) * HD + dof] = hi;
                *(uint32_t*)&Cl[(base + sr + 8) * HD + dof] = lo;
            } else {
                const size_t mrow = (size_t)(m0 + wm * 32 + (lane >> 2) + mi * 16);
                *(float2*)&C[mrow       * DIM + cbase + nt * 8 + ccol] = v0;
                *(float2*)&C[(mrow + 8) * DIM + cbase + nt * 8 + ccol] = v1;
            }
        }
    }
}

__global__ __launch_bounds__(256)
void qkv_mma_kernel(const bf16* __restrict__ xh, const bf16* __restrict__ xl,
                    const bf16* __restrict__ wh, const bf16* __restrict__ wl,
                    const float* __restrict__ bq, const float* __restrict__ bk,
                    const float* __restrict__ bv)
{
    const int z = blockIdx.z;
    const bf16* Wh = wh + (size_t)z * DIM * DIM;
    const bf16* Wl = wl + (size_t)z * DIM * DIM;
    const float* bias = (z == 0) ? bq : (z == 1) ? bk : bv;
    bf16* Ch = (z == 0) ? g_qh : (z == 1) ? g_kh : g_vh;
    bf16* Cl = (z == 0) ? g_ql : (z == 1) ? g_kl : g_vl;
    gemm_mma_body<1>(xh, xl, Wh, Wl, bias, nullptr, Ch, Cl);
}

__global__ __launch_bounds__(256)
void out_mma_kernel(const bf16* __restrict__ ah, const bf16* __restrict__ al,
                    const bf16* __restrict__ wh, const bf16* __restrict__ wl,
                    const float* __restrict__ bias, float* __restrict__ C)
{
    gemm_mma_body<0>(ah, al, wh + (size_t)3 * DIM * DIM, wl + (size_t)3 * DIM * DIM,
                     bias, C, nullptr, nullptr);
}

// ---------------------------------------------------------------------------
// HMMA flash-attention, cp.async-scheduled:
//   V(kt) streams in during QK^T+softmax;  K(kt+1) streams in during softmax+PV.
// ---------------------------------------------------------------------------
#define ALDT 72
#define SLDT 68
#define SMEM_ATTN (8 * 64 * ALDT * 2 + 64 * SLDT * 4 + 3 * 64 * 4)

__global__ __launch_bounds__(256, 2)
void attn_mma_kernel(const float* __restrict__ rel_emb)
{
    extern __shared__ __align__(16) char smem[];
    bf16* sQh = (bf16*)smem;
    bf16* sQl = sQh + 64 * ALDT;
    bf16* sKh = sQl + 64 * ALDT;
    bf16* sKl = sKh + 64 * ALDT;
    bf16* sVh = sKl + 64 * ALDT;
    bf16* sVl = sVh + 64 * ALDT;
    bf16* sPh = sVl + 64 * ALDT;
    bf16* sPl = sPh + 64 * ALDT;
    float* sS   = (float*)(sPl + 64 * ALDT);
    float* rowm = sS + 64 * SLDT;
    float* rowl = rowm + 64;
    float* rowf = rowl + 64;

    const int tid  = threadIdx.x;
    const int lane = tid & 31;
    const int wid  = tid >> 5;
    const int wm   = wid & 1;
    const int wn   = wid >> 1;
    const int qt = blockIdx.x, h = blockIdx.y, b = blockIdx.z;
    const size_t bhb = ((size_t)b * NH + h) * SEQ;

    const uint32_t uQh = smem_u32(sQh), uQl = smem_u32(sQl);
    const uint32_t uKh = smem_u32(sKh), uKl = smem_u32(sKl);
    const uint32_t uVh = smem_u32(sVh), uVl = smem_u32(sVl);
    const uint32_t uPh = smem_u32(sPh), uPl = smem_u32(sPl);

    // per-thread chunk coords for 64x64 bf16 tiles (512 x 16B, 2 per thread)
    const int cr0 = tid >> 3,           cs0 = (tid & 7) * 8;
    const int cr1 = (tid + 256) >> 3,   cs1 = (tid & 7) * 8;

    // Q tile (synchronous loads, once)
    {
        const bf16* Qhp = g_qh + (bhb + qt * 64) * HD;
        const bf16* Qlp = g_ql + (bhb + qt * 64) * HD;
#pragma unroll
        for (int i = 0; i < 2; i++) {
            const int f = tid + i * 256, r = f >> 3, s = (f & 7) * 8;
            *(uint4*)(sQh + r * ALDT + s) = *(const uint4*)(Qhp + r * HD + s);
            *(uint4*)(sQl + r * ALDT + s) = *(const uint4*)(Qlp + r * HD + s);
        }
    }
    if (tid < 64) { rowm[tid] = -1e30f; rowl[tid] = 0.0f; }

    const int aRow  = wm * 32 + (lane & 15);
    const int aK    = ((lane >> 4) & 1) * 8;
    const int bRow  = wn * 16 + (lane & 7) + ((lane >> 4) & 1) * 8;
    const int bK    = ((lane >> 3) & 1) * 8;
    const int vRowK = (lane & 7) + ((lane >> 3) & 1) * 8;
    const int vColD = wn * 16 + ((lane >> 4) & 1) * 8;

    float o[2][2][4];
#pragma unroll
    for (int mi = 0; mi < 2; mi++)
#pragma unroll
        for (int ni = 0; ni < 2; ni++)
#pragma unroll
            for (int t = 0; t < 4; t++) o[mi][ni][t] = 0.0f;

    const int NT = SEQ / 64;

    // preload K(0)
    {
        const bf16* Khp = g_kh + bhb * HD;
        const bf16* Klp = g_kl + bhb * HD;
        cpa16(uKh + (cr0 * ALDT + cs0) * 2, Khp + cr0 * HD + cs0);
        cpa16(uKl + (cr0 * ALDT + cs0) * 2, Klp + cr0 * HD + cs0);
        cpa16(uKh + (cr1 * ALDT + cs1) * 2, Khp + cr1 * HD + cs1);
        cpa16(uKl + (cr1 * ALDT + cs1) * 2, Klp + cr1 * HD + cs1);
        CPA_COMMIT();
    }

    for (int kt = 0; kt < NT; kt++) {
        // issue V(kt) — hidden behind QK + softmax
        {
            const bf16* Vhp = g_vh + (bhb + kt * 64) * HD;
            const bf16* Vlp = g_vl + (bhb + kt * 64) * HD;
            cpa16(uVh + (cr0 * ALDT + cs0) * 2, Vhp + cr0 * HD + cs0);
            cpa16(uVl + (cr0 * ALDT + cs0) * 2, Vlp + cr0 * HD + cs0);
            cpa16(uVh + (cr1 * ALDT + cs1) * 2, Vhp + cr1 * HD + cs1);
            cpa16(uVl + (cr1 * ALDT + cs1) * 2, Vlp + cr1 * HD + cs1);
            CPA_COMMIT();
        }
        CPA_WAIT(1);          // K(kt) ready (V(kt) may be in flight)
        __syncthreads();

        // ---- QK^T (split-bf16, 3 terms) ----
        float sf[2][2][4];
#pragma unroll
        for (int mi = 0; mi < 2; mi++)
#pragma unroll
            for (int ni = 0; ni < 2; ni++)
#pragma unroll
                for (int t = 0; t < 4; t++) sf[mi][ni][t] = 0.0f;

#pragma unroll
        for (int ks = 0; ks < 4; ks++) {
            uint32_t qh0[4], qh1[4], ql0[4], ql1[4], kh[4], kl[4];
            const int ko = ks * 16 + aK;
            ldsm4(qh0, uQh + ((aRow)      * ALDT + ko) * 2);
            ldsm4(qh1, uQh + ((aRow + 16) * ALDT + ko) * 2);
            ldsm4(ql0, uQl + ((aRow)      * ALDT + ko) * 2);
            ldsm4(ql1, uQl + ((aRow + 16) * ALDT + ko) * 2);
            const int kb = ks * 16 + bK;
            ldsm4(kh, uKh + (bRow * ALDT + kb) * 2);
            ldsm4(kl, uKl + (bRow * ALDT + kb) * 2);
#pragma unroll
            for (int ni = 0; ni < 2; ni++) {
                mma_bf(sf[0][ni], qh0, kh[2 * ni], kh[2 * ni + 1]);
                mma_bf(sf[1][ni], qh1, kh[2 * ni], kh[2 * ni + 1]);
                mma_bf(sf[0][ni], ql0, kh[2 * ni], kh[2 * ni + 1]);
                mma_bf(sf[1][ni], ql1, kh[2 * ni], kh[2 * ni + 1]);
                mma_bf(sf[0][ni], qh0, kl[2 * ni], kl[2 * ni + 1]);
                mma_bf(sf[1][ni], qh1, kl[2 * ni], kl[2 * ni + 1]);
            }
        }
        {
            const int r0 = wm * 32 + (lane >> 2);
            const int c0 = wn * 16 + 2 * (lane & 3);
#pragma unroll
            for (int mi = 0; mi < 2; mi++)
#pragma unroll
                for (int ni = 0; ni < 2; ni++) {
                    const int rr = r0 + mi * 16, cc = c0 + ni * 8;
                    *(float2*)&sS[rr * SLDT + cc] =
                        make_float2(sf[mi][ni][0] * 0.125f, sf[mi][ni][1] * 0.125f);
                    *(float2*)&sS[(rr + 8) * SLDT + cc] =
                        make_float2(sf[mi][ni][2] * 0.125f, sf[mi][ni][3] * 0.125f);
                }
        }
        __syncthreads();      // S visible; also: all QK reads of K done

        // issue K(kt+1) — hidden behind softmax + PV
        if (kt + 1 < NT) {
            const bf16* Khp = g_kh + (bhb + (kt + 1) * 64) * HD;
            const bf16* Klp = g_kl + (bhb + (kt + 1) * 64) * HD;
            cpa16(uKh + (cr0 * ALDT + cs0) * 2, Khp + cr0 * HD + cs0);
            cpa16(uKl + (cr0 * ALDT + cs0) * 2, Klp + cr0 * HD + cs0);
            cpa16(uKh + (cr1 * ALDT + cs1) * 2, Khp + cr1 * HD + cs1);
            cpa16(uKl + (cr1 * ALDT + cs1) * 2, Klp + cr1 * HD + cs1);
            CPA_COMMIT();
        }

        // ---- online softmax: 4 threads per row ----
        {
            const int sr = tid >> 2, sq = tid & 3;
            const int cb = sq * 16;
            const int qi = qt * 64 + sr;
            float v[16], mx = -1e30f;
#pragma unroll
            for (int j = 0; j < 4; j++) {
                float4 t = *(float4*)&sS[sr * SLDT + cb + j * 4];
                float tv[4] = {t.x, t.y, t.z, t.w};
#pragma unroll
                for (int e = 0; e < 4; e++) {
                    const int kj = kt * 64 + cb + j * 4 + e;
                    int dlt = qi - kj;
                    dlt = max(-MAXD, min(MAXD, dlt));
                    const float sv = tv[e] + __ldg(rel_emb + (dlt + MAXD) * NH + h);
                    v[j * 4 + e] = sv;
                    mx = fmaxf(mx, sv);
                }
            }
            mx = fmaxf(mx, __shfl_xor_sync(0xFFFFFFFFu, mx, 1));
            mx = fmaxf(mx, __shfl_xor_sync(0xFFFFFFFFu, mx, 2));
            const float mo = rowm[sr];
            const float mn = fmaxf(mo, mx);
            float sum = 0.0f;
#pragma unroll
            for (int j2 = 0; j2 < 8; j2++) {
                const float p0 = __expf(v[2 * j2]     - mn);
                const float p1 = __expf(v[2 * j2 + 1] - mn);
                sum += p0 + p1;
                uint32_t hi, lo;
                split2(make_float2(p0, p1), hi, lo);
                *(uint32_t*)(sPh + sr * ALDT + cb + 2 * j2) = hi;
                *(uint32_t*)(sPl + sr * ALDT + cb + 2 * j2) = lo;
            }
            sum += __shfl_xor_sync(0xFFFFFFFFu, sum, 1);
            sum += __shfl_xor_sync(0xFFFFFFFFu, sum, 2);
            if (sq == 0) {
                const float fac = __expf(mo - mn);
                rowf[sr] = fac;
                rowm[sr] = mn;
                rowl[sr] = rowl[sr] * fac + sum;
            }
        }
        if (kt + 1 < NT) CPA_WAIT(1); else CPA_WAIT(0);   // V(kt) ready
        __syncthreads();      // P + V visible to all

        // ---- rescale O, then P@V (split-bf16, 3 terms) ----
        {
            const int rr = wm * 32 + (lane >> 2);
            const float f00 = rowf[rr], f01 = rowf[rr + 8];
            const float f10 = rowf[rr + 16], f11 = rowf[rr + 24];
#pragma unroll
            for (int ni = 0; ni < 2; ni++) {
                o[0][ni][0] *= f00; o[0][ni][1] *= f00;
                o[0][ni][2] *= f01; o[0][ni][3] *= f01;
                o[1][ni][0] *= f10; o[1][ni][1] *= f10;
                o[1][ni][2] *= f11; o[1][ni][3] *= f11;
            }
        }
#pragma unroll
        for (int ks = 0; ks < 4; ks++) {
            uint32_t ph0[4], ph1[4], pl0[4], pl1[4], vh[4], vl[4];
            const int ko = ks * 16 + aK;
            ldsm4(ph0, uPh + ((aRow)      * ALDT + ko) * 2);
            ldsm4(ph1, uPh + ((aRow + 16) * ALDT + ko) * 2);
            ldsm4(pl0, uPl + ((aRow)      * ALDT + ko) * 2);
            ldsm4(pl1, uPl + ((aRow + 16) * ALDT + ko) * 2);
            const int kr = ks * 16 + vRowK;
            ldsm4t(vh, uVh + (kr * ALDT + vColD) * 2);
            ldsm4t(vl, uVl + (kr * ALDT + vColD) * 2);
#pragma unroll
            for (int ni = 0; ni < 2; ni++) {
                mma_bf(o[0][ni], ph0, vh[2 * ni], vh[2 * ni + 1]);
                mma_bf(o[1][ni], ph1, vh[2 * ni], vh[2 * ni + 1]);
                mma_bf(o[0][ni], pl0, vh[2 * ni], vh[2 * ni + 1]);
                mma_bf(o[1][ni], pl1, vh[2 * ni], vh[2 * ni + 1]);
                mma_bf(o[0][ni], ph0, vl[2 * ni], vl[2 * ni + 1]);
                mma_bf(o[1][ni], ph1, vl[2 * ni], vl[2 * ni + 1]);
            }
        }
        __syncthreads();      // all PV reads of V/P done before next iter overwrites
    }

    // ---- epilogue: normalize, split to bf16 hi/lo, write [B,S,H*Hd] ----
    {
        const int rr = wm * 32 + (lane >> 2);
        const float i00 = 1.0f / rowl[rr],      i01 = 1.0f / rowl[rr + 8];
        const float i10 = 1.0f / rowl[rr + 16], i11 = 1.0f / rowl[rr + 24];
        const int c0 = wn * 16 + 2 * (lane & 3);
#pragma unroll
        for (int mi = 0; mi < 2; mi++)
#pragma unroll
            for (int ni = 0; ni < 2; ni++) {
                const float iv0 = mi ? i10 : i00;
                const float iv1 = mi ? i11 : i01;
                const int row0 = qt * 64 + wm * 32 + mi * 16 + (lane >> 2);
                const int col  = h * HD + c0 + ni * 8;
                const size_t a0 = ((size_t)b * SEQ + row0)     * DIM + col;
                const size_t a1 = ((size_t)b * SEQ + row0 + 8) * DIM + col;
                uint32_t hi, lo;
                split2(make_float2(o[mi][ni][0] * iv0, o[mi][ni][1] * iv0), hi, lo);
                *(uint32_t*)(g_ath + a0) = hi;
                *(uint32_t*)(g_atl + a0) = lo;
                split2(make_float2(o[mi][ni][2] * iv1, o[mi][ni][3] * iv1), hi, lo);
                *(uint32_t*)(g_ath + a1) = hi;
                *(uint32_t*)(g_atl + a1) = lo;
            }
    }
}

// ---------------------------------------------------------------------------
extern "C" void kernel_launch(void* const* d_in, const int* in_sizes, int n_in,
                              void* d_out, int out_size)
{
    const float* x   = (const float*)d_in[0];
    const float* Wq  = (const float*)d_in[1];
    const float* bq  = (const float*)d_in[2];
    const float* Wk  = (const float*)d_in[3];
    const float* bk  = (const float*)d_in[4];
    const float* Wv  = (const float*)d_in[5];
    const float* bv  = (const float*)d_in[6];
    const float* Wo  = (const float*)d_in[7];
    const float* bo  = (const float*)d_in[8];
    const float* rel = (const float*)d_in[9];
    float* out = (float*)d_out;

    bf16 *xh, *xl, *wh, *wl, *ath, *atl;
    cudaGetSymbolAddress((void**)&xh,  g_xh);
    cudaGetSymbolAddress((void**)&xl,  g_xl);
    cudaGetSymbolAddress((void**)&wh,  g_wh);
    cudaGetSymbolAddress((void**)&wl,  g_wl);
    cudaGetSymbolAddress((void**)&ath, g_ath);
    cudaGetSymbolAddress((void**)&atl, g_atl);

    split_all_kernel<<<4096 + 4 * 1024, 256>>>(x, Wq, Wk, Wv, Wo);

    cudaFuncSetAttribute(qkv_mma_kernel, cudaFuncAttributeMaxDynamicSharedMemorySize, SMEM_GEMM);
    cudaFuncSetAttribute(out_mma_kernel, cudaFuncAttributeMaxDynamicSharedMemorySize, SMEM_GEMM);
    cudaFuncSetAttribute(attn_mma_kernel, cudaFuncAttributeMaxDynamicSharedMemorySize, SMEM_ATTN);

    dim3 gq(DIM / 128, MTOT / 128, 3);
    qkv_mma_kernel<<<gq, 256, SMEM_GEMM>>>(xh, xl, wh, wl, bq, bk, bv);

    dim3 ga(SEQ / 64, NH, BATCH);
    attn_mma_kernel<<<ga, 256, SMEM_ATTN>>>(rel);

    dim3 go(DIM / 128, MTOT / 128);
    out_mma_kernel<<<go, 256, SMEM_GEMM>>>(ath, atl, wh, wl, bo, out);
}

// round 9
// speedup vs baseline: 5.6067x; 1.2036x over previous
#include <cuda_runtime.h>
#include <cuda_bf16.h>
#include <cstdint>

#define BATCH 2
#define SEQ   2048
#define DIM   1024
#define NH    16
#define HD    64
#define MAXD  128
#define MTOT  (BATCH * SEQ)

typedef __nv_bfloat16 bf16;

// Scratch (static device allocations are allowed)
__device__ bf16 g_xh[MTOT * DIM];
__device__ bf16 g_xl[MTOT * DIM];
__device__ bf16 g_wh[4 * DIM * DIM];
__device__ bf16 g_wl[4 * DIM * DIM];
__device__ bf16 g_qh[MTOT * DIM];
__device__ bf16 g_ql[MTOT * DIM];
__device__ bf16 g_kh[MTOT * DIM];
__device__ bf16 g_kl[MTOT * DIM];
__device__ bf16 g_vh[MTOT * DIM];
__device__ bf16 g_vl[MTOT * DIM];
__device__ bf16 g_ath[MTOT * DIM];
__device__ bf16 g_atl[MTOT * DIM];

// ---------------------------------------------------------------------------
// helpers
// ---------------------------------------------------------------------------
__device__ __forceinline__ uint32_t smem_u32(const void* p) {
    uint32_t a;
    asm("{ .reg .u64 t; cvta.to.shared.u64 t, %1; cvt.u32.u64 %0, t; }" : "=r"(a) : "l"(p));
    return a;
}
__device__ __forceinline__ void ldsm4(uint32_t* r, uint32_t addr) {
    asm volatile("ldmatrix.sync.aligned.m8n8.x4.shared.b16 {%0,%1,%2,%3}, [%4];"
                 : "=r"(r[0]), "=r"(r[1]), "=r"(r[2]), "=r"(r[3]) : "r"(addr));
}
__device__ __forceinline__ void ldsm4t(uint32_t* r, uint32_t addr) {
    asm volatile("ldmatrix.sync.aligned.m8n8.x4.trans.shared.b16 {%0,%1,%2,%3}, [%4];"
                 : "=r"(r[0]), "=r"(r[1]), "=r"(r[2]), "=r"(r[3]) : "r"(addr));
}
__device__ __forceinline__ void mma_bf(float* d, const uint32_t* a, uint32_t b0, uint32_t b1) {
    asm volatile("mma.sync.aligned.m16n8k16.row.col.f32.bf16.bf16.f32 "
                 "{%0,%1,%2,%3}, {%4,%5,%6,%7}, {%8,%9}, {%0,%1,%2,%3};"
                 : "+f"(d[0]), "+f"(d[1]), "+f"(d[2]), "+f"(d[3])
                 : "r"(a[0]), "r"(a[1]), "r"(a[2]), "r"(a[3]), "r"(b0), "r"(b1));
}
__device__ __forceinline__ void cpa16(uint32_t dst, const void* src) {
    asm volatile("cp.async.cg.shared.global [%0], [%1], 16;" :: "r"(dst), "l"(src));
}
#define CPA_COMMIT() asm volatile("cp.async.commit_group;" ::: "memory")
#define CPA_WAIT(n)  asm volatile("cp.async.wait_group %0;" :: "n"(n) : "memory")

__device__ __forceinline__ uint32_t pack_bf2(bf16 a, bf16 b) {
    __nv_bfloat162 t(a, b);
    return *reinterpret_cast<uint32_t*>(&t);
}
__device__ __forceinline__ void split2(float2 v, uint32_t& hi, uint32_t& lo) {
    bf16 h0 = __float2bfloat16_rn(v.x);
    bf16 l0 = __float2bfloat16_rn(v.x - __bfloat162float(h0));
    bf16 h1 = __float2bfloat16_rn(v.y);
    bf16 l1 = __float2bfloat16_rn(v.y - __bfloat162float(h1));
    hi = pack_bf2(h0, h1);
    lo = pack_bf2(l0, l1);
}

// ---------------------------------------------------------------------------
// one-shot split of x + 4 weights -> bf16 hi/lo
// ---------------------------------------------------------------------------
__global__ __launch_bounds__(256)
void split_all_kernel(const float* __restrict__ x,
                      const float* __restrict__ Wq, const float* __restrict__ Wk,
                      const float* __restrict__ Wv, const float* __restrict__ Wo)
{
    const int bid = blockIdx.x;
    const float* in;
    bf16 *hi, *lo;
    int i;
    if (bid < 4096) {
        in = x; hi = g_xh; lo = g_xl;
        i = bid * 256 + threadIdx.x;
    } else {
        const int z  = (bid - 4096) >> 10;
        const int lb = (bid - 4096) & 1023;
        in = (z == 0) ? Wq : (z == 1) ? Wk : (z == 2) ? Wv : Wo;
        hi = g_wh + (size_t)z * DIM * DIM;
        lo = g_wl + (size_t)z * DIM * DIM;
        i = lb * 256 + threadIdx.x;
    }
    float4 v = ((const float4*)in)[i];
    uint32_t h0, l0, h1, l1;
    split2(make_float2(v.x, v.y), h0, l0);
    split2(make_float2(v.z, v.w), h1, l1);
    ((uint2*)hi)[i] = make_uint2(h0, h1);
    ((uint2*)lo)[i] = make_uint2(l0, l1);
}

// ---------------------------------------------------------------------------
// HMMA split-bf16 GEMM with 2-stage cp.async pipeline (unchanged from R7).
// ---------------------------------------------------------------------------
#define BK2  32
#define LDT2 40
#define TSTRIDE (128 * LDT2)
#define STG  (4 * TSTRIDE)
#define SMEM_GEMM (2 * STG * 2)

template <int SCATTER>
__device__ __forceinline__ void gemm_mma_body(
    const bf16* __restrict__ Ah, const bf16* __restrict__ Al,
    const bf16* __restrict__ Wh, const bf16* __restrict__ Wl,
    const float* __restrict__ bias, float* __restrict__ C,
    bf16* __restrict__ Ch, bf16* __restrict__ Cl)
{
    extern __shared__ __align__(16) char smem_raw[];
    bf16* smem = (bf16*)smem_raw;

    const int tid  = threadIdx.x;
    const int lane = tid & 31;
    const int wid  = tid >> 5;
    const int wm   = wid & 3;
    const int wn   = wid >> 2;
    const int m0   = blockIdx.y * 128;
    const int n0   = blockIdx.x * 128;

    float d[2][8][4];
#pragma unroll
    for (int i = 0; i < 2; i++)
#pragma unroll
        for (int j = 0; j < 8; j++)
#pragma unroll
            for (int t = 0; t < 4; t++) d[i][j][t] = 0.0f;

    const int aRow = wm * 32 + (lane & 15);
    const int aK   = (lane >> 4) * 8;
    const int bRow = wn * 64 + (lane & 7) + ((lane >> 4) << 3);
    const int bK   = ((lane >> 3) & 1) * 8;

    const uint32_t sb = smem_u32(smem);

    auto issue_stage = [&](int c, int st) {
        const int k0 = c * BK2;
        const uint32_t ub = sb + (uint32_t)(st * STG) * 2;
#pragma unroll
        for (int i = 0; i < 2; i++) {
            const int f = tid + i * 256;
            const int r = f >> 2;
            const int s = (f & 3) * 8;
            const size_t goA = (size_t)(m0 + r) * DIM + k0 + s;
            const size_t goW = (size_t)(n0 + r) * DIM + k0 + s;
            const uint32_t so = (uint32_t)(r * LDT2 + s) * 2;
            cpa16(ub + 0 * TSTRIDE * 2 + so, Ah + goA);
            cpa16(ub + 1 * TSTRIDE * 2 + so, Al + goA);
            cpa16(ub + 2 * TSTRIDE * 2 + so, Wh + goW);
            cpa16(ub + 3 * TSTRIDE * 2 + so, Wl + goW);
        }
        CPA_COMMIT();
    };

    issue_stage(0, 0);
    for (int c = 0; c < DIM / BK2; c++) {
        const int st = c & 1;
        if (c + 1 < DIM / BK2) { issue_stage(c + 1, st ^ 1); CPA_WAIT(1); }
        else                   { CPA_WAIT(0); }
        __syncthreads();

        const uint32_t ub  = sb + (uint32_t)(st * STG) * 2;
        const uint32_t uAh = ub;
        const uint32_t uAl = ub + 1 * TSTRIDE * 2;
        const uint32_t uWh = ub + 2 * TSTRIDE * 2;
        const uint32_t uWl = ub + 3 * TSTRIDE * 2;

#pragma unroll
        for (int ks = 0; ks < 2; ks++) {
            const int ko = aK + ks * 16;
            uint32_t ah0[4], ah1[4], al0[4], al1[4];
            ldsm4(ah0, uAh + ((aRow)      * LDT2 + ko) * 2);
            ldsm4(ah1, uAh + ((aRow + 16) * LDT2 + ko) * 2);
            ldsm4(al0, uAl + ((aRow)      * LDT2 + ko) * 2);
            ldsm4(al1, uAl + ((aRow + 16) * LDT2 + ko) * 2);
            const int kb = bK + ks * 16;
#pragma unroll
            for (int np = 0; np < 4; np++) {
                uint32_t bh[4], bl[4];
                ldsm4(bh, uWh + ((bRow + np * 16) * LDT2 + kb) * 2);
                ldsm4(bl, uWl + ((bRow + np * 16) * LDT2 + kb) * 2);
                const int n2 = np * 2;
                mma_bf(d[0][n2],     ah0, bh[0], bh[1]);
                mma_bf(d[0][n2 + 1], ah0, bh[2], bh[3]);
                mma_bf(d[1][n2],     ah1, bh[0], bh[1]);
                mma_bf(d[1][n2 + 1], ah1, bh[2], bh[3]);
                mma_bf(d[0][n2],     al0, bh[0], bh[1]);
                mma_bf(d[0][n2 + 1], al0, bh[2], bh[3]);
                mma_bf(d[1][n2],     al1, bh[0], bh[1]);
                mma_bf(d[1][n2 + 1], al1, bh[2], bh[3]);
                mma_bf(d[0][n2],     ah0, bl[0], bl[1]);
                mma_bf(d[0][n2 + 1], ah0, bl[2], bl[3]);
                mma_bf(d[1][n2],     ah1, bl[0], bl[1]);
                mma_bf(d[1][n2 + 1], ah1, bl[2], bl[3]);
            }
        }
        __syncthreads();
    }

    const int bidx  = m0 / SEQ;
    const int srow0 = (m0 - bidx * SEQ) + wm * 32 + (lane >> 2);
    const int cbase = n0 + wn * 64;
    const int ccol  = 2 * (lane & 3);
#pragma unroll
    for (int nt = 0; nt < 8; nt++) {
        const float2 bb = *(const float2*)(bias + cbase + nt * 8 + ccol);
#pragma unroll
        for (int mi = 0; mi < 2; mi++) {
            const int sr = srow0 + mi * 16;
            float2 v0 = make_float2(d[mi][nt][0] + bb.x, d[mi][nt][1] + bb.y);
            float2 v1 = make_float2(d[mi][nt][2] + bb.x, d[mi][nt][3] + bb.y);
            if (SCATTER) {
                const int h   = cbase >> 6;
                const int dof = nt * 8 + ccol;
                const size_t base = ((size_t)bidx * NH + h) * SEQ;
                uint32_t hi, lo;
                split2(v0, hi, lo);
                *(uint32_t*)&Ch[(base + sr) * HD + dof] = hi;
                *(uint32_t*)&Cl[(base + sr) * HD + dof] = lo;
                split2(v1, hi, lo);
                *(uint32_t*)&Ch[(base + sr + 8) * HD + dof] = hi;
                *(uint32_t*)&Cl[(base + sr + 8) * HD + dof] = lo;
            } else {
                const size_t mrow = (size_t)(m0 + wm * 32 + (lane >> 2) + mi * 16);
                *(float2*)&C[mrow       * DIM + cbase + nt * 8 + ccol] = v0;
                *(float2*)&C[(mrow + 8) * DIM + cbase + nt * 8 + ccol] = v1;
            }
        }
    }
}

__global__ __launch_bounds__(256)
void qkv_mma_kernel(const bf16* __restrict__ xh, const bf16* __restrict__ xl,
                    const bf16* __restrict__ wh, const bf16* __restrict__ wl,
                    const float* __restrict__ bq, const float* __restrict__ bk,
                    const float* __restrict__ bv)
{
    const int z = blockIdx.z;
    const bf16* Wh = wh + (size_t)z * DIM * DIM;
    const bf16* Wl = wl + (size_t)z * DIM * DIM;
    const float* bias = (z == 0) ? bq : (z == 1) ? bk : bv;
    bf16* Ch = (z == 0) ? g_qh : (z == 1) ? g_kh : g_vh;
    bf16* Cl = (z == 0) ? g_ql : (z == 1) ? g_kl : g_vl;
    gemm_mma_body<1>(xh, xl, Wh, Wl, bias, nullptr, Ch, Cl);
}

__global__ __launch_bounds__(256)
void out_mma_kernel(const bf16* __restrict__ ah, const bf16* __restrict__ al,
                    const bf16* __restrict__ wh, const bf16* __restrict__ wl,
                    const float* __restrict__ bias, float* __restrict__ C)
{
    gemm_mma_body<0>(ah, al, wh + (size_t)3 * DIM * DIM, wl + (size_t)3 * DIM * DIM,
                     bias, C, nullptr, nullptr);
}

// ---------------------------------------------------------------------------
// Register-resident FA2 attention: 4 warps/CTA, warp owns 16 q-rows x 64 keys.
// S C-fragments repack directly as P A-fragments (no S/P smem roundtrip).
// Softmax state (m, l) in registers; bias clamp hoisted for |qt-kt| >= 3.
// ---------------------------------------------------------------------------
#define ALDT 72
#define ATILE (64 * ALDT)                 // bf16 elems per tensor tile
#define SMEM_ATTN (6 * ATILE * 2)         // Qh Ql Kh Kl Vh Vl = 55296 B

__global__ __launch_bounds__(128)
void attn_mma_kernel(const float* __restrict__ rel_emb)
{
    extern __shared__ __align__(16) char smem[];
    bf16* sQh = (bf16*)smem;
    bf16* sQl = sQh + ATILE;
    bf16* sKh = sQl + ATILE;
    bf16* sKl = sKh + ATILE;
    bf16* sVh = sKl + ATILE;
    bf16* sVl = sVh + ATILE;

    const int tid  = threadIdx.x;
    const int lane = tid & 31;
    const int w    = tid >> 5;
    const int qt = blockIdx.x, h = blockIdx.y, b = blockIdx.z;
    const size_t bhb = ((size_t)b * NH + h) * SEQ;

    const uint32_t uQh = smem_u32(sQh), uQl = smem_u32(sQl);
    const uint32_t uKh = smem_u32(sKh), uKl = smem_u32(sKl);
    const uint32_t uVh = smem_u32(sVh), uVl = smem_u32(sVl);

    // Q tile 64x64 hi/lo, synchronous (128 threads x 4 chunks per tensor)
    {
        const bf16* Qhp = g_qh + (bhb + qt * 64) * HD;
        const bf16* Qlp = g_ql + (bhb + qt * 64) * HD;
#pragma unroll
        for (int i = 0; i < 4; i++) {
            const int f = tid + i * 128, r = f >> 3, s = (f & 7) * 8;
            *(uint4*)(sQh + r * ALDT + s) = *(const uint4*)(Qhp + r * HD + s);
            *(uint4*)(sQl + r * ALDT + s) = *(const uint4*)(Qlp + r * HD + s);
        }
    }

    // preload K(0)
    {
        const bf16* Khp = g_kh + bhb * HD;
        const bf16* Klp = g_kl + bhb * HD;
#pragma unroll
        for (int i = 0; i < 4; i++) {
            const int f = tid + i * 128, r = f >> 3, s = (f & 7) * 8;
            cpa16(uKh + (r * ALDT + s) * 2, Khp + r * HD + s);
            cpa16(uKl + (r * ALDT + s) * 2, Klp + r * HD + s);
        }
        CPA_COMMIT();
    }
    __syncthreads();   // Q visible

    // Q fragments hoisted out of the loop
    const int aRow = w * 16 + (lane & 15);
    const int aK   = ((lane >> 4) & 1) * 8;
    uint32_t qh[4][4], ql[4][4];
#pragma unroll
    for (int ks = 0; ks < 4; ks++) {
        ldsm4(qh[ks], uQh + (aRow * ALDT + ks * 16 + aK) * 2);
        ldsm4(ql[ks], uQl + (aRow * ALDT + ks * 16 + aK) * 2);
    }

    // fragment lane geometry
    const int bRowL = (lane & 7) + ((lane >> 4) & 1) * 8;   // + p*16 (QK B)
    const int bKoff = ((lane >> 3) & 1) * 8;
    const int vRowL = (lane & 7) + ((lane >> 3) & 1) * 8;   // + t*16 (PV B, trans)
    const int vColL = ((lane >> 4) & 1) * 8;                // + nd*16

    const int r0  = lane >> 2;
    const int qiA = qt * 64 + w * 16 + r0;
    const int cq  = 2 * (lane & 3);

    float o[8][4];
#pragma unroll
    for (int nt = 0; nt < 8; nt++)
#pragma unroll
        for (int t = 0; t < 4; t++) o[nt][t] = 0.0f;

    float mA = -1e30f, mB = -1e30f, lA = 0.0f, lB = 0.0f;

    const float bclo = __ldg(rel_emb + 0 * NH + h);          // dlt <= -128
    const float bchi = __ldg(rel_emb + 2 * MAXD * NH + h);   // dlt >= +128

    const int NT = SEQ / 64;
    for (int kt = 0; kt < NT; kt++) {
        // issue V(kt) — prev PV finished (trailing barrier)
        {
            const bf16* Vhp = g_vh + (bhb + kt * 64) * HD;
            const bf16* Vlp = g_vl + (bhb + kt * 64) * HD;
#pragma unroll
            for (int i = 0; i < 4; i++) {
                const int f = tid + i * 128, r = f >> 3, s = (f & 7) * 8;
                cpa16(uVh + (r * ALDT + s) * 2, Vhp + r * HD + s);
                cpa16(uVl + (r * ALDT + s) * 2, Vlp + r * HD + s);
            }
            CPA_COMMIT();
        }
        CPA_WAIT(1);          // K(kt) complete (V in flight)
        __syncthreads();      // K visible to all

        // ---- QK^T: S = Q K^T, C-fragments in sf ----
        float sf[8][4];
#pragma unroll
        for (int nt = 0; nt < 8; nt++)
#pragma unroll
            for (int t = 0; t < 4; t++) sf[nt][t] = 0.0f;

#pragma unroll
        for (int ks = 0; ks < 4; ks++) {
            const int kb = ks * 16 + bKoff;
#pragma unroll
            for (int p = 0; p < 4; p++) {
                uint32_t kh[4], kl[4];
                const uint32_t ro = ((p * 16 + bRowL) * ALDT + kb) * 2;
                ldsm4(kh, uKh + ro);
                ldsm4(kl, uKl + ro);
                const int nt = p * 2;
                mma_bf(sf[nt],     qh[ks], kh[0], kh[1]);
                mma_bf(sf[nt + 1], qh[ks], kh[2], kh[3]);
                mma_bf(sf[nt],     ql[ks], kh[0], kh[1]);
                mma_bf(sf[nt + 1], ql[ks], kh[2], kh[3]);
                mma_bf(sf[nt],     qh[ks], kl[0], kl[1]);
                mma_bf(sf[nt + 1], qh[ks], kl[2], kl[3]);
            }
        }

        // ---- bias + online softmax, fully in registers ----
        {
            const int dq = qt - kt;
            if (dq >= 3 || dq <= -3) {
                const float bc = (dq >= 3) ? bchi : bclo;
#pragma unroll
                for (int nt = 0; nt < 8; nt++)
#pragma unroll
                    for (int t = 0; t < 4; t++) sf[nt][t] = sf[nt][t] * 0.125f + bc;
            } else {
                const int colb = kt * 64 + cq;
#pragma unroll
                for (int nt = 0; nt < 8; nt++) {
#pragma unroll
                    for (int j = 0; j < 2; j++) {
                        const int col = colb + nt * 8 + j;
                        int dA = qiA - col;
                        dA = max(-MAXD, min(MAXD, dA));
                        int dB = qiA + 8 - col;
                        dB = max(-MAXD, min(MAXD, dB));
                        sf[nt][j]     = sf[nt][j]     * 0.125f + __ldg(rel_emb + (dA + MAXD) * NH + h);
                        sf[nt][2 + j] = sf[nt][2 + j] * 0.125f + __ldg(rel_emb + (dB + MAXD) * NH + h);
                    }
                }
            }

            float mxA = -1e30f, mxB = -1e30f;
#pragma unroll
            for (int nt = 0; nt < 8; nt++) {
                mxA = fmaxf(mxA, fmaxf(sf[nt][0], sf[nt][1]));
                mxB = fmaxf(mxB, fmaxf(sf[nt][2], sf[nt][3]));
            }
            mxA = fmaxf(mxA, __shfl_xor_sync(0xFFFFFFFFu, mxA, 1));
            mxA = fmaxf(mxA, __shfl_xor_sync(0xFFFFFFFFu, mxA, 2));
            mxB = fmaxf(mxB, __shfl_xor_sync(0xFFFFFFFFu, mxB, 1));
            mxB = fmaxf(mxB, __shfl_xor_sync(0xFFFFFFFFu, mxB, 2));

            const float mnA = fmaxf(mA, mxA);
            const float mnB = fmaxf(mB, mxB);
            const float facA = __expf(mA - mnA);
            const float facB = __expf(mB - mnB);
            mA = mnA; mB = mnB;

            float sumA = 0.0f, sumB = 0.0f;
#pragma unroll
            for (int nt = 0; nt < 8; nt++) {
                sf[nt][0] = __expf(sf[nt][0] - mnA);
                sf[nt][1] = __expf(sf[nt][1] - mnA);
                sf[nt][2] = __expf(sf[nt][2] - mnB);
                sf[nt][3] = __expf(sf[nt][3] - mnB);
                sumA += sf[nt][0] + sf[nt][1];
                sumB += sf[nt][2] + sf[nt][3];
            }
            sumA += __shfl_xor_sync(0xFFFFFFFFu, sumA, 1);
            sumA += __shfl_xor_sync(0xFFFFFFFFu, sumA, 2);
            sumB += __shfl_xor_sync(0xFFFFFFFFu, sumB, 1);
            sumB += __shfl_xor_sync(0xFFFFFFFFu, sumB, 2);
            lA = lA * facA + sumA;
            lB = lB * facB + sumB;

            // rescale O
#pragma unroll
            for (int nt = 0; nt < 8; nt++) {
                o[nt][0] *= facA; o[nt][1] *= facA;
                o[nt][2] *= facB; o[nt][3] *= facB;
            }
        }

        // ---- P fragments straight from S C-fragments ----
        uint32_t ph[4][4], pl[4][4];
#pragma unroll
        for (int t = 0; t < 4; t++) {
            split2(make_float2(sf[2 * t][0],     sf[2 * t][1]),     ph[t][0], pl[t][0]);
            split2(make_float2(sf[2 * t][2],     sf[2 * t][3]),     ph[t][1], pl[t][1]);
            split2(make_float2(sf[2 * t + 1][0], sf[2 * t + 1][1]), ph[t][2], pl[t][2]);
            split2(make_float2(sf[2 * t + 1][2], sf[2 * t + 1][3]), ph[t][3], pl[t][3]);
        }

        CPA_WAIT(0);          // V(kt) complete
        __syncthreads();      // V visible; all warps done reading K

        // issue K(kt+1) — hidden behind PV
        if (kt + 1 < NT) {
            const bf16* Khp = g_kh + (bhb + (kt + 1) * 64) * HD;
            const bf16* Klp = g_kl + (bhb + (kt + 1) * 64) * HD;
#pragma unroll
            for (int i = 0; i < 4; i++) {
                const int f = tid + i * 128, r = f >> 3, s = (f & 7) * 8;
                cpa16(uKh + (r * ALDT + s) * 2, Khp + r * HD + s);
                cpa16(uKl + (r * ALDT + s) * 2, Klp + r * HD + s);
            }
            CPA_COMMIT();
        }

        // ---- P @ V ----
#pragma unroll
        for (int t = 0; t < 4; t++) {
            const int kr = t * 16 + vRowL;
#pragma unroll
            for (int nd = 0; nd < 4; nd++) {
                uint32_t vh[4], vl[4];
                const uint32_t vo = (kr * ALDT + nd * 16 + vColL) * 2;
                ldsm4t(vh, uVh + vo);
                ldsm4t(vl, uVl + vo);
                const int ntd = nd * 2;
                mma_bf(o[ntd],     ph[t], vh[0], vh[1]);
                mma_bf(o[ntd + 1], ph[t], vh[2], vh[3]);
                mma_bf(o[ntd],     pl[t], vh[0], vh[1]);
                mma_bf(o[ntd + 1], pl[t], vh[2], vh[3]);
                mma_bf(o[ntd],     ph[t], vl[0], vl[1]);
                mma_bf(o[ntd + 1], ph[t], vl[2], vl[3]);
            }
        }
        __syncthreads();      // PV reads done before next V issue
    }

    // ---- epilogue: normalize, split, write [B,S,H*Hd] as bf16 hi/lo ----
    {
        const float iA = 1.0f / lA, iB = 1.0f / lB;
        const int rowA = qt * 64 + w * 16 + r0;
#pragma unroll
        for (int nt = 0; nt < 8; nt++) {
            const int col = h * HD + nt * 8 + cq;
            const size_t a0 = ((size_t)b * SEQ + rowA)     * DIM + col;
            const size_t a1 = ((size_t)b * SEQ + rowA + 8) * DIM + col;
            uint32_t hi, lo;
            split2(make_float2(o[nt][0] * iA, o[nt][1] * iA), hi, lo);
            *(uint32_t*)(g_ath + a0) = hi;
            *(uint32_t*)(g_atl + a0) = lo;
            split2(make_float2(o[nt][2] * iB, o[nt][3] * iB), hi, lo);
            *(uint32_t*)(g_ath + a1) = hi;
            *(uint32_t*)(g_atl + a1) = lo;
        }
    }
}

// ---------------------------------------------------------------------------
extern "C" void kernel_launch(void* const* d_in, const int* in_sizes, int n_in,
                              void* d_out, int out_size)
{
    const float* x   = (const float*)d_in[0];
    const float* Wq  = (const float*)d_in[1];
    const float* bq  = (const float*)d_in[2];
    const float* Wk  = (const float*)d_in[3];
    const float* bk  = (const float*)d_in[4];
    const float* Wv  = (const float*)d_in[5];
    const float* bv  = (const float*)d_in[6];
    const float* Wo  = (const float*)d_in[7];
    const float* bo  = (const float*)d_in[8];
    const float* rel = (const float*)d_in[9];
    float* out = (float*)d_out;

    bf16 *xh, *xl, *wh, *wl, *ath, *atl;
    cudaGetSymbolAddress((void**)&xh,  g_xh);
    cudaGetSymbolAddress((void**)&xl,  g_xl);
    cudaGetSymbolAddress((void**)&wh,  g_wh);
    cudaGetSymbolAddress((void**)&wl,  g_wl);
    cudaGetSymbolAddress((void**)&ath, g_ath);
    cudaGetSymbolAddress((void**)&atl, g_atl);

    split_all_kernel<<<4096 + 4 * 1024, 256>>>(x, Wq, Wk, Wv, Wo);

    cudaFuncSetAttribute(qkv_mma_kernel, cudaFuncAttributeMaxDynamicSharedMemorySize, SMEM_GEMM);
    cudaFuncSetAttribute(out_mma_kernel, cudaFuncAttributeMaxDynamicSharedMemorySize, SMEM_GEMM);
    cudaFuncSetAttribute(attn_mma_kernel, cudaFuncAttributeMaxDynamicSharedMemorySize, SMEM_ATTN);

    dim3 gq(DIM / 128, MTOT / 128, 3);
    qkv_mma_kernel<<<gq, 256, SMEM_GEMM>>>(xh, xl, wh, wl, bq, bk, bv);

    dim3 ga(SEQ / 64, NH, BATCH);
    attn_mma_kernel<<<ga, 128, SMEM_ATTN>>>(rel);

    dim3 go(DIM / 128, MTOT / 128);
    out_mma_kernel<<<go, 256, SMEM_GEMM>>>(ath, atl, wh, wl, bo, out);
}